// round 2
// baseline (speedup 1.0000x reference)
#include <cuda_runtime.h>
#include <cuda_bf16.h>

#define NN   50000
#define EE   800000
#define DIN  128
#define DH   512
#define DOUT 256
#define GG   512

// Scratch (static __device__ — no allocations allowed). 16B-aligned for float4.
__device__ __align__(16) float g_h0[NN * DIN];   // x + neighbor-sum   (25.6 MB)
__device__ __align__(16) float g_hA[NN * DH];    // ping               (102.4 MB)
__device__ __align__(16) float g_hB[NN * DH];    // pong               (102.4 MB)
__device__ __align__(16) float g_pool[GG * DH];  // per-graph sums
__device__ float g_cnt[GG];                      // per-graph node counts

// ---------------------------------------------------------------------------
// h0 = x  (eps_GIN = 0 so (1+eps)*x == x)
__global__ void copy_x_kernel(const float* __restrict__ x) {
    int i = blockIdx.x * blockDim.x + threadIdx.x;
    if (i < NN * DIN / 4) {
        ((float4*)g_h0)[i] = ((const float4*)x)[i];
    }
}

// h0[dst] += x[src] for every edge. One thread per (edge, 4-float chunk).
// NOTE: edge_index is int32 on device (JAX x64 disabled downcasts int64->int32).
__global__ void edge_agg_kernel(const float* __restrict__ x,
                                const int* __restrict__ ei) {
    long long idx = (long long)blockIdx.x * blockDim.x + threadIdx.x;
    if (idx >= (long long)EE * (DIN / 4)) return;
    int e = (int)(idx >> 5);          // DIN/4 = 32 chunks per edge
    int c = ((int)idx & 31) * 4;
    int src = __ldg(&ei[e]);
    int dst = __ldg(&ei[EE + e]);
    float4 v = *(const float4*)(x + (size_t)src * DIN + c);
    float* p = g_h0 + (size_t)dst * DIN + c;
    atomicAdd(p + 0, v.x);
    atomicAdd(p + 1, v.y);
    atomicAdd(p + 2, v.z);
    atomicAdd(p + 3, v.w);
}

// ---------------------------------------------------------------------------
// C[M,N] = act(A[M,K] @ B[K,N] + bias), row-major everywhere.
// BM=BN=64, BK=16, 256 threads, 4x4 microtile per thread.
// ACT: 0 = none, 1 = LeakyReLU(1.5), 2 = ReLU
template <int ACT>
__global__ void gemm_bias_act_kernel(const float* __restrict__ A,
                                     const float* __restrict__ B,
                                     const float* __restrict__ bias,
                                     float* __restrict__ C,
                                     int M, int K, int N) {
    __shared__ float As[16][64];   // [k][m]
    __shared__ float Bs[16][64];   // [k][n]

    int tid = threadIdx.x;
    int tx = tid & 15;             // 0..15 -> n
    int ty = tid >> 4;             // 0..15 -> m
    int m0 = blockIdx.y * 64;
    int n0 = blockIdx.x * 64;

    float acc[4][4] = {};

    for (int k0 = 0; k0 < K; k0 += 16) {
        // A tile: 64 rows x 16 cols, one float4 per thread
        {
            int row = tid >> 2;            // 0..63
            int c4  = (tid & 3) * 4;       // 0,4,8,12
            float4 v = make_float4(0.f, 0.f, 0.f, 0.f);
            if (m0 + row < M)
                v = *(const float4*)(A + (size_t)(m0 + row) * K + k0 + c4);
            As[c4 + 0][row] = v.x;
            As[c4 + 1][row] = v.y;
            As[c4 + 2][row] = v.z;
            As[c4 + 3][row] = v.w;
        }
        // B tile: 16 rows x 64 cols, one float4 per thread
        {
            int row = tid >> 4;            // 0..15
            int c4  = (tid & 15) * 4;      // 0..60
            float4 v = *(const float4*)(B + (size_t)(k0 + row) * N + n0 + c4);
            *(float4*)&Bs[row][c4] = v;
        }
        __syncthreads();

#pragma unroll
        for (int k = 0; k < 16; k++) {
            float4 a = *(float4*)&As[k][ty * 4];
            float4 b = *(float4*)&Bs[k][tx * 4];
            float av[4] = {a.x, a.y, a.z, a.w};
            float bv[4] = {b.x, b.y, b.z, b.w};
#pragma unroll
            for (int i = 0; i < 4; i++)
#pragma unroll
                for (int j = 0; j < 4; j++)
                    acc[i][j] += av[i] * bv[j];
        }
        __syncthreads();
    }

    // Epilogue: bias + activation, vectorized store
#pragma unroll
    for (int i = 0; i < 4; i++) {
        int r = m0 + ty * 4 + i;
        if (r >= M) continue;
        int c = n0 + tx * 4;
        float4 bv = *(const float4*)(bias + c);
        float o[4] = {acc[i][0] + bv.x, acc[i][1] + bv.y,
                      acc[i][2] + bv.z, acc[i][3] + bv.w};
#pragma unroll
        for (int j = 0; j < 4; j++) {
            if (ACT == 1) o[j] = o[j] > 0.f ? o[j] : 1.5f * o[j];
            if (ACT == 2) o[j] = o[j] > 0.f ? o[j] : 0.f;
        }
        *(float4*)(C + (size_t)r * N + c) =
            make_float4(o[0], o[1], o[2], o[3]);
    }
}

// ---------------------------------------------------------------------------
__global__ void zero_pool_kernel() {
    int i = blockIdx.x * blockDim.x + threadIdx.x;
    if (i < GG * DH) g_pool[i] = 0.f;
    if (i < GG) g_cnt[i] = 0.f;
}

// pool[batch[n]] += h[n]; one thread per (node, 4-float chunk of DH)
__global__ void pool_add_kernel(const int* __restrict__ batch) {
    int idx = blockIdx.x * blockDim.x + threadIdx.x;
    if (idx >= NN * (DH / 4)) return;
    int node = idx >> 7;                 // DH/4 = 128
    int c = (idx & 127) * 4;
    int b = __ldg(&batch[node]);
    float4 v = *(const float4*)(g_hB + (size_t)node * DH + c);
    float* p = g_pool + (size_t)b * DH + c;
    atomicAdd(p + 0, v.x);
    atomicAdd(p + 1, v.y);
    atomicAdd(p + 2, v.z);
    atomicAdd(p + 3, v.w);
    if (c == 0) atomicAdd(&g_cnt[b], 1.0f);
}

// out[g] = normalize( (pool[g]/cnt[g]) @ Wl + bl )
// One block (256 threads = DOUT) per graph.
__global__ void final_out_kernel(const float* __restrict__ Wl,
                                 const float* __restrict__ bl,
                                 float* __restrict__ out) {
    __shared__ float p[DH];
    __shared__ float red[DOUT];
    int g = blockIdx.x;
    int t = threadIdx.x;

    float inv_cnt = 1.0f / fmaxf(g_cnt[g], 1.0f);
    for (int k = t; k < DH; k += DOUT)
        p[k] = g_pool[g * DH + k] * inv_cnt;
    __syncthreads();

    float acc = bl[t];
#pragma unroll 8
    for (int k = 0; k < DH; k++)
        acc += p[k] * Wl[k * DOUT + t];

    red[t] = acc * acc;
    __syncthreads();
    for (int s = DOUT / 2; s > 0; s >>= 1) {
        if (t < s) red[t] += red[t + s];
        __syncthreads();
    }
    float nrm = fmaxf(sqrtf(red[0]), 1e-12f);
    out[g * DOUT + t] = acc / nrm;
}

// ---------------------------------------------------------------------------
extern "C" void kernel_launch(void* const* d_in, const int* in_sizes, int n_in,
                              void* d_out, int out_size) {
    const float* x     = (const float*)d_in[0];
    const int*   ei    = (const int*)d_in[1];     // int32 (JAX x64 disabled)
    const int*   batch = (const int*)d_in[2];     // int32
    const float* W1 = (const float*)d_in[3];
    const float* b1 = (const float*)d_in[4];
    const float* W2 = (const float*)d_in[5];
    const float* b2 = (const float*)d_in[6];
    const float* W3 = (const float*)d_in[7];
    const float* b3 = (const float*)d_in[8];
    const float* W4 = (const float*)d_in[9];
    const float* b4 = (const float*)d_in[10];
    const float* Wl = (const float*)d_in[11];
    const float* bl = (const float*)d_in[12];
    float* out = (float*)d_out;

    float *h0, *hA, *hB;
    cudaGetSymbolAddress((void**)&h0, g_h0);
    cudaGetSymbolAddress((void**)&hA, g_hA);
    cudaGetSymbolAddress((void**)&hB, g_hB);

    // 1) h0 = x ; h0[dst] += x[src]
    copy_x_kernel<<<(NN * DIN / 4 + 255) / 256, 256>>>(x);
    edge_agg_kernel<<<(int)(((long long)EE * 32 + 255) / 256), 256>>>(x, ei);

    // 2) 4-layer MLP
    dim3 gridN(DH / 64, (NN + 63) / 64);
    gemm_bias_act_kernel<1><<<gridN, 256>>>(h0, W1, b1, hA, NN, DIN, DH);
    gemm_bias_act_kernel<2><<<gridN, 256>>>(hA, W2, b2, hB, NN, DH, DH);
    gemm_bias_act_kernel<2><<<gridN, 256>>>(hB, W3, b3, hA, NN, DH, DH);
    gemm_bias_act_kernel<0><<<gridN, 256>>>(hA, W4, b4, hB, NN, DH, DH);

    // 3) global mean pool
    zero_pool_kernel<<<(GG * DH + 255) / 256, 256>>>();
    pool_add_kernel<<<(NN * (DH / 4) + 255) / 256, 256>>>(batch);

    // 4) final linear + L2 normalize
    final_out_kernel<<<GG, DOUT>>>(Wl, bl, out);
}

// round 3
// speedup vs baseline: 1.1490x; 1.1490x over previous
#include <cuda_runtime.h>
#include <cuda_bf16.h>

#define NN   50000
#define EE   800000
#define DIN  128
#define DH   512
#define DOUT 256
#define GG   512

// Scratch (static __device__ — no allocations allowed). 16B-aligned for float4.
__device__ __align__(16) float g_h0[NN * DIN];   // x + neighbor-sum   (25.6 MB)
__device__ __align__(16) float g_hA[NN * DH];    // ping               (102.4 MB)
__device__ __align__(16) float g_hB[NN * DH];    // pong               (102.4 MB)
__device__ __align__(16) float g_pool[GG * DH];  // per-graph sums
__device__ float g_cnt[GG];                      // per-graph node counts

// ---------------------------------------------------------------------------
// h0 = x  (eps_GIN = 0 so (1+eps)*x == x)
__global__ void copy_x_kernel(const float* __restrict__ x) {
    int i = blockIdx.x * blockDim.x + threadIdx.x;
    if (i < NN * DIN / 4) {
        ((float4*)g_h0)[i] = ((const float4*)x)[i];
    }
}

// h0[dst] += x[src] for every edge. One thread per (edge, 4-float chunk).
__global__ void edge_agg_kernel(const float* __restrict__ x,
                                const int* __restrict__ ei) {
    long long idx = (long long)blockIdx.x * blockDim.x + threadIdx.x;
    if (idx >= (long long)EE * (DIN / 4)) return;
    int e = (int)(idx >> 5);          // DIN/4 = 32 chunks per edge
    int c = ((int)idx & 31) * 4;
    int src = __ldg(&ei[e]);
    int dst = __ldg(&ei[EE + e]);
    float4 v = *(const float4*)(x + (size_t)src * DIN + c);
    float* p = g_h0 + (size_t)dst * DIN + c;
    atomicAdd(p + 0, v.x);
    atomicAdd(p + 1, v.y);
    atomicAdd(p + 2, v.z);
    atomicAdd(p + 3, v.w);
}

// ---------------------------------------------------------------------------
// C[M,N] = act(A[M,K] @ B[K,N] + bias), row-major.
// BM=128, BN=128, BK=8. 256 threads. 8x8 microtile per thread (as 2x2 groups
// of 4x4 to keep LDS fragment loads conflict-free). Double-buffered smem.
// ACT: 0 = none, 1 = LeakyReLU(1.5), 2 = ReLU
template <int ACT>
__global__ __launch_bounds__(256, 2)
void gemm128_kernel(const float* __restrict__ A,
                    const float* __restrict__ B,
                    const float* __restrict__ bias,
                    float* __restrict__ C,
                    int M, int K, int N) {
    __shared__ float As[2][8][128];   // [buf][k][m]
    __shared__ float Bs[2][8][128];   // [buf][k][n]

    const int tid  = threadIdx.x;
    const int warp = tid >> 5;
    const int lane = tid & 31;
    const int wm = (warp >> 1) * 32;        // warp m-origin within tile (0,32,64,96)
    const int wn = (warp & 1) * 64;         // warp n-origin within tile (0,64)
    const int lm = (lane >> 3) * 4;         // lane m-subgroup (0,4,8,12)
    const int ln = (lane & 7) * 4;          // lane n-subgroup (0..28)
    const int m0 = blockIdx.y * 128;
    const int n0 = blockIdx.x * 128;

    // Global-load mapping
    const int a_row = tid >> 1;             // 0..127
    const int a_k4  = (tid & 1) * 4;        // 0 or 4
    const int b_row = tid >> 5;             // 0..7
    const int b_c4  = lane * 4;             // 0..124

    float acc[2][2][4][4] = {};             // [im][in][i][j]

    // ---- preload tile 0 ----
    {
        float4 av = make_float4(0.f, 0.f, 0.f, 0.f);
        if (m0 + a_row < M)
            av = *(const float4*)(A + (size_t)(m0 + a_row) * K + a_k4);
        As[0][a_k4 + 0][a_row] = av.x;
        As[0][a_k4 + 1][a_row] = av.y;
        As[0][a_k4 + 2][a_row] = av.z;
        As[0][a_k4 + 3][a_row] = av.w;
        float4 bv = *(const float4*)(B + (size_t)b_row * N + n0 + b_c4);
        *(float4*)&Bs[0][b_row][b_c4] = bv;
    }
    __syncthreads();

    int buf = 0;
    for (int k0 = 0; k0 < K; k0 += 8) {
        const bool has_next = (k0 + 8 < K);
        float4 anv, bnv;
        if (has_next) {
            anv = make_float4(0.f, 0.f, 0.f, 0.f);
            if (m0 + a_row < M)
                anv = *(const float4*)(A + (size_t)(m0 + a_row) * K + (k0 + 8) + a_k4);
            bnv = *(const float4*)(B + (size_t)(k0 + 8 + b_row) * N + n0 + b_c4);
        }

#pragma unroll
        for (int k = 0; k < 8; k++) {
            float4 a0 = *(float4*)&As[buf][k][wm + lm];
            float4 a1 = *(float4*)&As[buf][k][wm + lm + 16];
            float4 b0 = *(float4*)&Bs[buf][k][wn + ln];
            float4 b1 = *(float4*)&Bs[buf][k][wn + ln + 32];
            float a[2][4] = {{a0.x, a0.y, a0.z, a0.w},
                             {a1.x, a1.y, a1.z, a1.w}};
            float b[2][4] = {{b0.x, b0.y, b0.z, b0.w},
                             {b1.x, b1.y, b1.z, b1.w}};
#pragma unroll
            for (int im = 0; im < 2; im++)
#pragma unroll
                for (int i = 0; i < 4; i++)
#pragma unroll
                    for (int in = 0; in < 2; in++)
#pragma unroll
                        for (int j = 0; j < 4; j++)
                            acc[im][in][i][j] += a[im][i] * b[in][j];
        }

        if (has_next) {
            int nb = buf ^ 1;
            As[nb][a_k4 + 0][a_row] = anv.x;
            As[nb][a_k4 + 1][a_row] = anv.y;
            As[nb][a_k4 + 2][a_row] = anv.z;
            As[nb][a_k4 + 3][a_row] = anv.w;
            *(float4*)&Bs[nb][b_row][b_c4] = bnv;
        }
        __syncthreads();
        buf ^= 1;
    }

    // ---- epilogue: bias + activation ----
#pragma unroll
    for (int im = 0; im < 2; im++) {
#pragma unroll
        for (int i = 0; i < 4; i++) {
            int r = m0 + wm + lm + im * 16 + i;
            if (r >= M) continue;
#pragma unroll
            for (int in = 0; in < 2; in++) {
                int c = n0 + wn + ln + in * 32;
                float4 bb = *(const float4*)(bias + c);
                float o[4] = {acc[im][in][i][0] + bb.x,
                              acc[im][in][i][1] + bb.y,
                              acc[im][in][i][2] + bb.z,
                              acc[im][in][i][3] + bb.w};
#pragma unroll
                for (int j = 0; j < 4; j++) {
                    if (ACT == 1) o[j] = o[j] > 0.f ? o[j] : 1.5f * o[j];
                    if (ACT == 2) o[j] = o[j] > 0.f ? o[j] : 0.f;
                }
                *(float4*)(C + (size_t)r * N + c) =
                    make_float4(o[0], o[1], o[2], o[3]);
            }
        }
    }
}

// ---------------------------------------------------------------------------
__global__ void zero_pool_kernel() {
    int i = blockIdx.x * blockDim.x + threadIdx.x;
    if (i < GG * DH) g_pool[i] = 0.f;
    if (i < GG) g_cnt[i] = 0.f;
}

// pool[batch[n]] += h[n]; one thread per (node, 4-float chunk of DH)
__global__ void pool_add_kernel(const int* __restrict__ batch) {
    int idx = blockIdx.x * blockDim.x + threadIdx.x;
    if (idx >= NN * (DH / 4)) return;
    int node = idx >> 7;                 // DH/4 = 128
    int c = (idx & 127) * 4;
    int b = __ldg(&batch[node]);
    float4 v = *(const float4*)(g_hB + (size_t)node * DH + c);
    float* p = g_pool + (size_t)b * DH + c;
    atomicAdd(p + 0, v.x);
    atomicAdd(p + 1, v.y);
    atomicAdd(p + 2, v.z);
    atomicAdd(p + 3, v.w);
    if (c == 0) atomicAdd(&g_cnt[b], 1.0f);
}

// out[g] = normalize( (pool[g]/cnt[g]) @ Wl + bl )
__global__ void final_out_kernel(const float* __restrict__ Wl,
                                 const float* __restrict__ bl,
                                 float* __restrict__ out) {
    __shared__ float p[DH];
    __shared__ float red[DOUT];
    int g = blockIdx.x;
    int t = threadIdx.x;

    float inv_cnt = 1.0f / fmaxf(g_cnt[g], 1.0f);
    for (int k = t; k < DH; k += DOUT)
        p[k] = g_pool[g * DH + k] * inv_cnt;
    __syncthreads();

    float acc = bl[t];
#pragma unroll 8
    for (int k = 0; k < DH; k++)
        acc += p[k] * Wl[k * DOUT + t];

    red[t] = acc * acc;
    __syncthreads();
    for (int s = DOUT / 2; s > 0; s >>= 1) {
        if (t < s) red[t] += red[t + s];
        __syncthreads();
    }
    float nrm = fmaxf(sqrtf(red[0]), 1e-12f);
    out[g * DOUT + t] = acc / nrm;
}

// ---------------------------------------------------------------------------
extern "C" void kernel_launch(void* const* d_in, const int* in_sizes, int n_in,
                              void* d_out, int out_size) {
    const float* x     = (const float*)d_in[0];
    const int*   ei    = (const int*)d_in[1];     // int32 on device
    const int*   batch = (const int*)d_in[2];     // int32 on device
    const float* W1 = (const float*)d_in[3];
    const float* b1 = (const float*)d_in[4];
    const float* W2 = (const float*)d_in[5];
    const float* b2 = (const float*)d_in[6];
    const float* W3 = (const float*)d_in[7];
    const float* b3 = (const float*)d_in[8];
    const float* W4 = (const float*)d_in[9];
    const float* b4 = (const float*)d_in[10];
    const float* Wl = (const float*)d_in[11];
    const float* bl = (const float*)d_in[12];
    float* out = (float*)d_out;

    float *h0, *hA, *hB;
    cudaGetSymbolAddress((void**)&h0, g_h0);
    cudaGetSymbolAddress((void**)&hA, g_hA);
    cudaGetSymbolAddress((void**)&hB, g_hB);

    // 1) h0 = x ; h0[dst] += x[src]
    copy_x_kernel<<<(NN * DIN / 4 + 255) / 256, 256>>>(x);
    edge_agg_kernel<<<(int)(((long long)EE * 32 + 255) / 256), 256>>>(x, ei);

    // 2) 4-layer MLP (128x128 tiles)
    dim3 gridN(DH / 128, (NN + 127) / 128);
    gemm128_kernel<1><<<gridN, 256>>>(h0, W1, b1, hA, NN, DIN, DH);
    gemm128_kernel<2><<<gridN, 256>>>(hA, W2, b2, hB, NN, DH, DH);
    gemm128_kernel<2><<<gridN, 256>>>(hB, W3, b3, hA, NN, DH, DH);
    gemm128_kernel<0><<<gridN, 256>>>(hA, W4, b4, hB, NN, DH, DH);

    // 3) global mean pool
    zero_pool_kernel<<<(GG * DH + 255) / 256, 256>>>();
    pool_add_kernel<<<(NN * (DH / 4) + 255) / 256, 256>>>(batch);

    // 4) final linear + L2 normalize
    final_out_kernel<<<GG, DOUT>>>(Wl, bl, out);
}

// round 6
// speedup vs baseline: 1.9276x; 1.6777x over previous
#include <cuda_runtime.h>
#include <cuda_bf16.h>
#include <cstdint>

#define NN   50000
#define EE   800000
#define DIN  128
#define DH   512
#define DOUT 256
#define GG   512

// ---------------------------------------------------------------------------
// Device scratch (no allocations allowed)
__device__ __align__(16) float g_h0[NN * DIN];     // x + neighbor-sum (fp32)
__device__ __align__(16) float g_hF[NN * DH];      // layer-4 fp32 output
__device__ __align__(16) float g_pool[GG * DH];
__device__ float g_cnt[GG];

// Activation ping-pong, bf16 hi/lo split
__device__ __align__(16) __nv_bfloat16 g_a0h[NN * DH];
__device__ __align__(16) __nv_bfloat16 g_a0l[NN * DH];
__device__ __align__(16) __nv_bfloat16 g_a1h[NN * DH];
__device__ __align__(16) __nv_bfloat16 g_a1l[NN * DH];

// Weights, transposed to [n][k] (K-major rows) and split hi/lo
__device__ __align__(16) __nv_bfloat16 g_w1h[DH * DIN], g_w1l[DH * DIN];
__device__ __align__(16) __nv_bfloat16 g_w2h[DH * DH],  g_w2l[DH * DH];
__device__ __align__(16) __nv_bfloat16 g_w3h[DH * DH],  g_w3l[DH * DH];
__device__ __align__(16) __nv_bfloat16 g_w4h[DH * DH],  g_w4l[DH * DH];

// ---------------------------------------------------------------------------
// h0 = x
__global__ void copy_x_kernel(const float* __restrict__ x) {
    int i = blockIdx.x * blockDim.x + threadIdx.x;
    if (i < NN * DIN / 4) ((float4*)g_h0)[i] = ((const float4*)x)[i];
}

// h0[dst] += x[src]
__global__ void edge_agg_kernel(const float* __restrict__ x,
                                const int* __restrict__ ei) {
    long long idx = (long long)blockIdx.x * blockDim.x + threadIdx.x;
    if (idx >= (long long)EE * (DIN / 4)) return;
    int e = (int)(idx >> 5);
    int c = ((int)idx & 31) * 4;
    int src = __ldg(&ei[e]);
    int dst = __ldg(&ei[EE + e]);
    float4 v = *(const float4*)(x + (size_t)src * DIN + c);
    float* p = g_h0 + (size_t)dst * DIN + c;
    atomicAdd(p + 0, v.x);
    atomicAdd(p + 1, v.y);
    atomicAdd(p + 2, v.z);
    atomicAdd(p + 3, v.w);
}

// fp32 -> (bf16 hi, bf16 lo) for layer-0 input (stride DIN)
__global__ void split_x_kernel() {
    int i = blockIdx.x * blockDim.x + threadIdx.x;
    if (i >= NN * DIN) return;
    float f = g_h0[i];
    __nv_bfloat16 h = __float2bfloat16(f);
    __nv_bfloat16 l = __float2bfloat16(f - __bfloat162float(h));
    g_a0h[i] = h;
    g_a0l[i] = l;
}

// W[k][n] (row-major [Kd x 512]) -> Wt[n][k] split hi/lo
__global__ void splitW_kernel(const float* __restrict__ W, int Kd,
                              __nv_bfloat16* __restrict__ oh,
                              __nv_bfloat16* __restrict__ ol) {
    int i = blockIdx.x * blockDim.x + threadIdx.x;
    if (i >= 512 * Kd) return;
    int n = i / Kd;
    int k = i - n * Kd;
    float f = W[(size_t)k * 512 + n];
    __nv_bfloat16 h = __float2bfloat16(f);
    __nv_bfloat16 l = __float2bfloat16(f - __bfloat162float(h));
    oh[i] = h;
    ol[i] = l;
}

// ---------------------------------------------------------------------------
// mma.sync m16n8k16 bf16 (baseline PTX, works on compute_103)
__device__ __forceinline__ void mma16816(float* d, const uint32_t* a,
                                         const uint32_t* b) {
    asm volatile(
        "mma.sync.aligned.m16n8k16.row.col.f32.bf16.bf16.f32 "
        "{%0,%1,%2,%3}, {%4,%5,%6,%7}, {%8,%9}, {%0,%1,%2,%3};"
        : "+f"(d[0]), "+f"(d[1]), "+f"(d[2]), "+f"(d[3])
        : "r"(a[0]), "r"(a[1]), "r"(a[2]), "r"(a[3]), "r"(b[0]), "r"(b[1]));
}

// SMEM tile geometry: 128 rows x 32 k-cols, row stride 40 bf16 (80B).
// 80B stride => fragment LDS (8 rows x 4 k-pairs) is bank-conflict-free,
// and row starts stay 16B-aligned (80 = 5*16).
#define LDA        40
#define TILE_ELEM  (128 * LDA)                 // bf16 elements per tile
#define NTILES     4                           // Ah, Al, Bh, Bl
#define BUF_ELEM   (NTILES * TILE_ELEM)
#define GEMM_SMEM  (2 * BUF_ELEM * 2)          // bytes (double buffer)

// Load one 128x32 chunk (global, K-major, ld = Kd) into registers (2 x uint4)
__device__ __forceinline__ void ld_chunk(uint4* r, const __nv_bfloat16* __restrict__ g,
                                         int row0, int rowMax, int ld, int kb, int tid) {
#pragma unroll
    for (int j = 0; j < 2; j++) {
        int idx = tid + 256 * j;          // 0..511
        int row = idx >> 2;               // 0..127
        int seg = idx & 3;                // 0..3 (8 bf16 each)
        uint4 v = make_uint4(0u, 0u, 0u, 0u);
        int gr = row0 + row;
        if (gr < rowMax)
            v = *(const uint4*)(g + (size_t)gr * ld + kb + seg * 8);
        r[j] = v;
    }
}
__device__ __forceinline__ void st_chunk(__nv_bfloat16* s, const uint4* r, int tid) {
#pragma unroll
    for (int j = 0; j < 2; j++) {
        int idx = tid + 256 * j;
        int row = idx >> 2;
        int seg = idx & 3;
        *(uint4*)(s + row * LDA + seg * 8) = r[j];
    }
}

// ---------------------------------------------------------------------------
// C[M,512] = act(A @ Wt^T + bias); A = Ah+Al, Wt = Bh+Bl (bf16 split, 3 MMA passes).
// CTA tile 128x128, 8 warps as 2(m) x 4(n), warp tile 64x32. K-chunk 32.
// ACT: 0 -> fp32 out (Of); 1 -> LeakyReLU(1.5) split out; 2 -> ReLU split out.
template <int ACT>
__global__ __launch_bounds__(256, 2)
void gemm_mma_kernel(const __nv_bfloat16* __restrict__ Ah,
                     const __nv_bfloat16* __restrict__ Al,
                     const __nv_bfloat16* __restrict__ Bh,
                     const __nv_bfloat16* __restrict__ Bl,
                     const float* __restrict__ bias,
                     __nv_bfloat16* __restrict__ Oh,
                     __nv_bfloat16* __restrict__ Ol,
                     float* __restrict__ Of,
                     int M, int Kd) {
    extern __shared__ __nv_bfloat16 smem[];

    const int tid  = threadIdx.x;
    const int warp = tid >> 5;
    const int lane = tid & 31;
    const int gid  = lane >> 2;        // group id 0..7
    const int tig  = lane & 3;         // thread-in-group 0..3
    const int wm = (warp >> 2) * 64;   // warp m origin (0, 64)
    const int wn = (warp & 3) * 32;    // warp n origin (0, 32, 64, 96)
    const int m0 = blockIdx.y * 128;
    const int n0 = blockIdx.x * 128;

    float acc[4][4][4] = {};           // [mt][nt][reg]

    const int NCHUNK = Kd >> 5;

    // preload chunk 0 -> buffer 0
    {
        uint4 r[4][2];
        ld_chunk(r[0], Ah, m0, M, Kd, 0, tid);
        ld_chunk(r[1], Al, m0, M, Kd, 0, tid);
        ld_chunk(r[2], Bh, n0, 1 << 30, Kd, 0, tid);
        ld_chunk(r[3], Bl, n0, 1 << 30, Kd, 0, tid);
        st_chunk(smem + 0 * TILE_ELEM, r[0], tid);
        st_chunk(smem + 1 * TILE_ELEM, r[1], tid);
        st_chunk(smem + 2 * TILE_ELEM, r[2], tid);
        st_chunk(smem + 3 * TILE_ELEM, r[3], tid);
    }
    __syncthreads();

    for (int c = 0; c < NCHUNK; c++) {
        const int buf = c & 1;
        const __nv_bfloat16* As_h = smem + buf * BUF_ELEM + 0 * TILE_ELEM;
        const __nv_bfloat16* As_l = smem + buf * BUF_ELEM + 1 * TILE_ELEM;
        const __nv_bfloat16* Bs_h = smem + buf * BUF_ELEM + 2 * TILE_ELEM;
        const __nv_bfloat16* Bs_l = smem + buf * BUF_ELEM + 3 * TILE_ELEM;

        // prefetch next chunk into registers
        uint4 pr[4][2];
        const bool has_next = (c + 1 < NCHUNK);
        if (has_next) {
            const int kb = (c + 1) * 32;
            ld_chunk(pr[0], Ah, m0, M, Kd, kb, tid);
            ld_chunk(pr[1], Al, m0, M, Kd, kb, tid);
            ld_chunk(pr[2], Bh, n0, 1 << 30, Kd, kb, tid);
            ld_chunk(pr[3], Bl, n0, 1 << 30, Kd, kb, tid);
        }

#pragma unroll
        for (int k0 = 0; k0 < 32; k0 += 16) {
            uint32_t bh[4][2], bl[4][2];
#pragma unroll
            for (int nt = 0; nt < 4; nt++) {
                int nrow = (wn + nt * 8 + gid) * LDA;
                bh[nt][0] = *(const uint32_t*)(Bs_h + nrow + k0 + 2 * tig);
                bh[nt][1] = *(const uint32_t*)(Bs_h + nrow + k0 + 8 + 2 * tig);
                bl[nt][0] = *(const uint32_t*)(Bs_l + nrow + k0 + 2 * tig);
                bl[nt][1] = *(const uint32_t*)(Bs_l + nrow + k0 + 8 + 2 * tig);
            }
#pragma unroll
            for (int mt = 0; mt < 4; mt++) {
                int r0 = (wm + mt * 16 + gid) * LDA;
                int r8 = r0 + 8 * LDA;
                uint32_t ah[4], al[4];
                ah[0] = *(const uint32_t*)(As_h + r0 + k0 + 2 * tig);
                ah[1] = *(const uint32_t*)(As_h + r8 + k0 + 2 * tig);
                ah[2] = *(const uint32_t*)(As_h + r0 + k0 + 8 + 2 * tig);
                ah[3] = *(const uint32_t*)(As_h + r8 + k0 + 8 + 2 * tig);
                al[0] = *(const uint32_t*)(As_l + r0 + k0 + 2 * tig);
                al[1] = *(const uint32_t*)(As_l + r8 + k0 + 2 * tig);
                al[2] = *(const uint32_t*)(As_l + r0 + k0 + 8 + 2 * tig);
                al[3] = *(const uint32_t*)(As_l + r8 + k0 + 8 + 2 * tig);
#pragma unroll
                for (int nt = 0; nt < 4; nt++) {
                    mma16816(acc[mt][nt], ah, bh[nt]);
                    mma16816(acc[mt][nt], ah, bl[nt]);
                    mma16816(acc[mt][nt], al, bh[nt]);
                }
            }
        }

        if (has_next) {
            __nv_bfloat16* nb = smem + (buf ^ 1) * BUF_ELEM;
            st_chunk(nb + 0 * TILE_ELEM, pr[0], tid);
            st_chunk(nb + 1 * TILE_ELEM, pr[1], tid);
            st_chunk(nb + 2 * TILE_ELEM, pr[2], tid);
            st_chunk(nb + 3 * TILE_ELEM, pr[3], tid);
        }
        __syncthreads();
    }

    // Epilogue: bias + activation (+ hi/lo re-split), fragment layout stores
#pragma unroll
    for (int mt = 0; mt < 4; mt++) {
        int m1 = m0 + wm + mt * 16 + gid;
        int m2 = m1 + 8;
#pragma unroll
        for (int nt = 0; nt < 4; nt++) {
            int n = n0 + wn + nt * 8 + 2 * tig;
            float2 bb = *(const float2*)(bias + n);
            float f0 = acc[mt][nt][0] + bb.x;
            float f1 = acc[mt][nt][1] + bb.y;
            float f2 = acc[mt][nt][2] + bb.x;
            float f3 = acc[mt][nt][3] + bb.y;
            if (ACT == 1) {
                f0 = f0 > 0.f ? f0 : 1.5f * f0;
                f1 = f1 > 0.f ? f1 : 1.5f * f1;
                f2 = f2 > 0.f ? f2 : 1.5f * f2;
                f3 = f3 > 0.f ? f3 : 1.5f * f3;
            } else if (ACT == 2) {
                f0 = fmaxf(f0, 0.f);
                f1 = fmaxf(f1, 0.f);
                f2 = fmaxf(f2, 0.f);
                f3 = fmaxf(f3, 0.f);
            }
            if (ACT == 0) {
                if (m1 < M) *(float2*)(Of + (size_t)m1 * DH + n) = make_float2(f0, f1);
                if (m2 < M) *(float2*)(Of + (size_t)m2 * DH + n) = make_float2(f2, f3);
            } else {
                if (m1 < M) {
                    __nv_bfloat16 h0 = __float2bfloat16(f0);
                    __nv_bfloat16 h1 = __float2bfloat16(f1);
                    __nv_bfloat162 hp; hp.x = h0; hp.y = h1;
                    __nv_bfloat162 lp;
                    lp.x = __float2bfloat16(f0 - __bfloat162float(h0));
                    lp.y = __float2bfloat16(f1 - __bfloat162float(h1));
                    *(__nv_bfloat162*)(Oh + (size_t)m1 * DH + n) = hp;
                    *(__nv_bfloat162*)(Ol + (size_t)m1 * DH + n) = lp;
                }
                if (m2 < M) {
                    __nv_bfloat16 h2 = __float2bfloat16(f2);
                    __nv_bfloat16 h3 = __float2bfloat16(f3);
                    __nv_bfloat162 hp; hp.x = h2; hp.y = h3;
                    __nv_bfloat162 lp;
                    lp.x = __float2bfloat16(f2 - __bfloat162float(h2));
                    lp.y = __float2bfloat16(f3 - __bfloat162float(h3));
                    *(__nv_bfloat162*)(Oh + (size_t)m2 * DH + n) = hp;
                    *(__nv_bfloat162*)(Ol + (size_t)m2 * DH + n) = lp;
                }
            }
        }
    }
}

// ---------------------------------------------------------------------------
__global__ void zero_pool_kernel() {
    int i = blockIdx.x * blockDim.x + threadIdx.x;
    if (i < GG * DH) g_pool[i] = 0.f;
    if (i < GG) g_cnt[i] = 0.f;
}

__global__ void pool_add_kernel(const int* __restrict__ batch) {
    int idx = blockIdx.x * blockDim.x + threadIdx.x;
    if (idx >= NN * (DH / 4)) return;
    int node = idx >> 7;
    int c = (idx & 127) * 4;
    int b = __ldg(&batch[node]);
    float4 v = *(const float4*)(g_hF + (size_t)node * DH + c);
    float* p = g_pool + (size_t)b * DH + c;
    atomicAdd(p + 0, v.x);
    atomicAdd(p + 1, v.y);
    atomicAdd(p + 2, v.z);
    atomicAdd(p + 3, v.w);
    if (c == 0) atomicAdd(&g_cnt[b], 1.0f);
}

__global__ void final_out_kernel(const float* __restrict__ Wl,
                                 const float* __restrict__ bl,
                                 float* __restrict__ out) {
    __shared__ float p[DH];
    __shared__ float red[DOUT];
    int g = blockIdx.x;
    int t = threadIdx.x;

    float inv_cnt = 1.0f / fmaxf(g_cnt[g], 1.0f);
    for (int k = t; k < DH; k += DOUT)
        p[k] = g_pool[g * DH + k] * inv_cnt;
    __syncthreads();

    float acc = bl[t];
#pragma unroll 8
    for (int k = 0; k < DH; k++)
        acc += p[k] * Wl[k * DOUT + t];

    red[t] = acc * acc;
    __syncthreads();
    for (int s = DOUT / 2; s > 0; s >>= 1) {
        if (t < s) red[t] += red[t + s];
        __syncthreads();
    }
    float nrm = fmaxf(sqrtf(red[0]), 1e-12f);
    out[g * DOUT + t] = acc / nrm;
}

// ---------------------------------------------------------------------------
extern "C" void kernel_launch(void* const* d_in, const int* in_sizes, int n_in,
                              void* d_out, int out_size) {
    const float* x     = (const float*)d_in[0];
    const int*   ei    = (const int*)d_in[1];
    const int*   batch = (const int*)d_in[2];
    const float* W1 = (const float*)d_in[3];
    const float* b1 = (const float*)d_in[4];
    const float* W2 = (const float*)d_in[5];
    const float* b2 = (const float*)d_in[6];
    const float* W3 = (const float*)d_in[7];
    const float* b3 = (const float*)d_in[8];
    const float* W4 = (const float*)d_in[9];
    const float* b4 = (const float*)d_in[10];
    const float* Wl = (const float*)d_in[11];
    const float* bl = (const float*)d_in[12];
    float* out = (float*)d_out;

    __nv_bfloat16 *a0h, *a0l, *a1h, *a1l;
    __nv_bfloat16 *w1h, *w1l, *w2h, *w2l, *w3h, *w3l, *w4h, *w4l;
    float* hF;
    cudaGetSymbolAddress((void**)&a0h, g_a0h);
    cudaGetSymbolAddress((void**)&a0l, g_a0l);
    cudaGetSymbolAddress((void**)&a1h, g_a1h);
    cudaGetSymbolAddress((void**)&a1l, g_a1l);
    cudaGetSymbolAddress((void**)&w1h, g_w1h);
    cudaGetSymbolAddress((void**)&w1l, g_w1l);
    cudaGetSymbolAddress((void**)&w2h, g_w2h);
    cudaGetSymbolAddress((void**)&w2l, g_w2l);
    cudaGetSymbolAddress((void**)&w3h, g_w3h);
    cudaGetSymbolAddress((void**)&w3l, g_w3l);
    cudaGetSymbolAddress((void**)&w4h, g_w4h);
    cudaGetSymbolAddress((void**)&w4l, g_w4l);
    cudaGetSymbolAddress((void**)&hF, g_hF);

    cudaFuncSetAttribute(gemm_mma_kernel<0>, cudaFuncAttributeMaxDynamicSharedMemorySize, GEMM_SMEM);
    cudaFuncSetAttribute(gemm_mma_kernel<1>, cudaFuncAttributeMaxDynamicSharedMemorySize, GEMM_SMEM);
    cudaFuncSetAttribute(gemm_mma_kernel<2>, cudaFuncAttributeMaxDynamicSharedMemorySize, GEMM_SMEM);

    // 1) aggregation + input split
    copy_x_kernel<<<(NN * DIN / 4 + 255) / 256, 256>>>(x);
    edge_agg_kernel<<<(int)(((long long)EE * 32 + 255) / 256), 256>>>(x, ei);
    split_x_kernel<<<(NN * DIN + 255) / 256, 256>>>();

    // 2) weight transpose + split
    splitW_kernel<<<(512 * DIN + 255) / 256, 256>>>(W1, DIN, w1h, w1l);
    splitW_kernel<<<(512 * DH + 255) / 256, 256>>>(W2, DH, w2h, w2l);
    splitW_kernel<<<(512 * DH + 255) / 256, 256>>>(W3, DH, w3h, w3l);
    splitW_kernel<<<(512 * DH + 255) / 256, 256>>>(W4, DH, w4h, w4l);

    // 3) 4-layer MLP on tensor cores (mma.sync bf16, 3-pass hi/lo split)
    dim3 grid(DH / 128, (NN + 127) / 128);
    gemm_mma_kernel<1><<<grid, 256, GEMM_SMEM>>>(a0h, a0l, w1h, w1l, b1, a1h, a1l, nullptr, NN, DIN);
    gemm_mma_kernel<2><<<grid, 256, GEMM_SMEM>>>(a1h, a1l, w2h, w2l, b2, a0h, a0l, nullptr, NN, DH);
    gemm_mma_kernel<2><<<grid, 256, GEMM_SMEM>>>(a0h, a0l, w3h, w3l, b3, a1h, a1l, nullptr, NN, DH);
    gemm_mma_kernel<0><<<grid, 256, GEMM_SMEM>>>(a1h, a1l, w4h, w4l, b4, nullptr, nullptr, hF, NN, DH);

    // 4) pool + final
    zero_pool_kernel<<<(GG * DH + 255) / 256, 256>>>();
    pool_add_kernel<<<(NN * (DH / 4) + 255) / 256, 256>>>(batch);
    final_out_kernel<<<GG, DOUT>>>(Wl, bl, out);
}

// round 7
// speedup vs baseline: 2.5486x; 1.3221x over previous
#include <cuda_runtime.h>
#include <cuda_bf16.h>
#include <cstdint>

#define NN   50000
#define EE   800000
#define DIN  128
#define DH   512
#define DOUT 256
#define GG   512

// ---------------------------------------------------------------------------
// Device scratch (no allocations allowed)
__device__ __align__(16) float g_h0[NN * DIN];     // x + neighbor-sum (fp32)
__device__ __align__(16) float g_pool[GG * DH];
__device__ float g_cnt[GG];

// Activation ping-pong, bf16 hi/lo split
__device__ __align__(16) __nv_bfloat16 g_a0h[NN * DH];
__device__ __align__(16) __nv_bfloat16 g_a0l[NN * DH];
__device__ __align__(16) __nv_bfloat16 g_a1h[NN * DH];
__device__ __align__(16) __nv_bfloat16 g_a1l[NN * DH];

// Weights, transposed to [n][k] (K-major rows) and split hi/lo
__device__ __align__(16) __nv_bfloat16 g_w1h[DH * DIN], g_w1l[DH * DIN];
__device__ __align__(16) __nv_bfloat16 g_w2h[DH * DH],  g_w2l[DH * DH];
__device__ __align__(16) __nv_bfloat16 g_w3h[DH * DH],  g_w3l[DH * DH];
__device__ __align__(16) __nv_bfloat16 g_w4h[DH * DH],  g_w4l[DH * DH];

// ---------------------------------------------------------------------------
__device__ __forceinline__ uint32_t smem_u32(const void* p) {
    uint32_t a;
    asm("{ .reg .u64 t; cvta.to.shared.u64 t, %1; cvt.u32.u64 %0, t; }"
        : "=r"(a) : "l"(p));
    return a;
}
#define CP16(dst, src) \
    asm volatile("cp.async.cg.shared.global [%0], [%1], 16;" :: "r"(dst), "l"(src))
#define CP_COMMIT() asm volatile("cp.async.commit_group;" ::: "memory")
#define CP_WAIT0()  asm volatile("cp.async.wait_group 0;" ::: "memory")
#define CP_WAIT1()  asm volatile("cp.async.wait_group 1;" ::: "memory")
#define LDSM_X4(r0, r1, r2, r3, addr) \
    asm volatile("ldmatrix.sync.aligned.m8n8.x4.shared.b16 {%0,%1,%2,%3}, [%4];" \
                 : "=r"(r0), "=r"(r1), "=r"(r2), "=r"(r3) : "r"(addr))

__device__ __forceinline__ void mma16816(float* d, const uint32_t* a,
                                         const uint32_t* b) {
    asm volatile(
        "mma.sync.aligned.m16n8k16.row.col.f32.bf16.bf16.f32 "
        "{%0,%1,%2,%3}, {%4,%5,%6,%7}, {%8,%9}, {%0,%1,%2,%3};"
        : "+f"(d[0]), "+f"(d[1]), "+f"(d[2]), "+f"(d[3])
        : "r"(a[0]), "r"(a[1]), "r"(a[2]), "r"(a[3]), "r"(b[0]), "r"(b[1]));
}

// ---------------------------------------------------------------------------
// h0 = x
__global__ void copy_x_kernel(const float* __restrict__ x) {
    int i = blockIdx.x * blockDim.x + threadIdx.x;
    if (i < NN * DIN / 4) ((float4*)g_h0)[i] = ((const float4*)x)[i];
}

// h0[dst] += x[src]
__global__ void edge_agg_kernel(const float* __restrict__ x,
                                const int* __restrict__ ei) {
    long long idx = (long long)blockIdx.x * blockDim.x + threadIdx.x;
    if (idx >= (long long)EE * (DIN / 4)) return;
    int e = (int)(idx >> 5);
    int c = ((int)idx & 31) * 4;
    int src = __ldg(&ei[e]);
    int dst = __ldg(&ei[EE + e]);
    float4 v = *(const float4*)(x + (size_t)src * DIN + c);
    float* p = g_h0 + (size_t)dst * DIN + c;
    atomicAdd(p + 0, v.x);
    atomicAdd(p + 1, v.y);
    atomicAdd(p + 2, v.z);
    atomicAdd(p + 3, v.w);
}

// fp32 -> (bf16 hi, bf16 lo)
__global__ void split_x_kernel() {
    int i = blockIdx.x * blockDim.x + threadIdx.x;
    if (i >= NN * DIN) return;
    float f = g_h0[i];
    __nv_bfloat16 h = __float2bfloat16(f);
    __nv_bfloat16 l = __float2bfloat16(f - __bfloat162float(h));
    g_a0h[i] = h;
    g_a0l[i] = l;
}

// W[k][n] -> Wt[n][k] split hi/lo
__global__ void splitW_kernel(const float* __restrict__ W, int Kd,
                              __nv_bfloat16* __restrict__ oh,
                              __nv_bfloat16* __restrict__ ol) {
    int i = blockIdx.x * blockDim.x + threadIdx.x;
    if (i >= 512 * Kd) return;
    int n = i / Kd;
    int k = i - n * Kd;
    float f = W[(size_t)k * 512 + n];
    __nv_bfloat16 h = __float2bfloat16(f);
    __nv_bfloat16 l = __float2bfloat16(f - __bfloat162float(h));
    oh[i] = h;
    ol[i] = l;
}

// ---------------------------------------------------------------------------
// SMEM tile: 128 rows x 32 k bf16, row stride 40 bf16 (80B) -> LDSM conflict-free
#define LDA         40
#define TILE_BYTES  (128 * LDA * 2)            // 10240
#define BUF_BYTES   (4 * TILE_BYTES)           // 40960
#define GEMM_SMEM   (2 * BUF_BYTES)            // 81920

__device__ __forceinline__ void issue_chunk(uint32_t sb,
                                            const __nv_bfloat16* __restrict__ Ah,
                                            const __nv_bfloat16* __restrict__ Al,
                                            const __nv_bfloat16* __restrict__ Bh,
                                            const __nv_bfloat16* __restrict__ Bl,
                                            int m0, int n0, int M, int Kd, int kb,
                                            int tid) {
#pragma unroll
    for (int j = 0; j < 2; j++) {
        int idx = tid + 256 * j;       // 0..511
        int row = idx >> 2;            // 0..127
        int seg = idx & 3;             // 0..3 (8 bf16 = 16B)
        uint32_t doff = row * (LDA * 2) + seg * 16;
        int ar = m0 + row;
        if (ar >= M) ar = M - 1;       // clamp: OOB rows computed but never stored
        int br = n0 + row;             // always < 512
        size_t ko = (size_t)kb + seg * 8;
        CP16(sb + 0 * TILE_BYTES + doff, Ah + (size_t)ar * Kd + ko);
        CP16(sb + 1 * TILE_BYTES + doff, Al + (size_t)ar * Kd + ko);
        CP16(sb + 2 * TILE_BYTES + doff, Bh + (size_t)br * Kd + ko);
        CP16(sb + 3 * TILE_BYTES + doff, Bl + (size_t)br * Kd + ko);
    }
}

// C[M,512] = act(A @ Wt^T + bias); A = Ah+Al, Wt = Bh+Bl (3 MMA passes).
// CTA 128x128, 8 warps = 2(m) x 4(n), warp tile 64x32, K-chunk 32, cp.async DB.
// ACT: 0 -> fused mean-pool atomics; 1 -> LeakyReLU(1.5) split; 2 -> ReLU split.
template <int ACT>
__global__ __launch_bounds__(256, 2)
void gemm_mma_kernel(const __nv_bfloat16* __restrict__ Ah,
                     const __nv_bfloat16* __restrict__ Al,
                     const __nv_bfloat16* __restrict__ Bh,
                     const __nv_bfloat16* __restrict__ Bl,
                     const float* __restrict__ bias,
                     __nv_bfloat16* __restrict__ Oh,
                     __nv_bfloat16* __restrict__ Ol,
                     const int* __restrict__ batch,
                     int M, int Kd) {
    extern __shared__ char smem[];
    const uint32_t s0 = smem_u32(smem);

    const int tid  = threadIdx.x;
    const int warp = tid >> 5;
    const int lane = tid & 31;
    const int gid  = lane >> 2;
    const int tig  = lane & 3;
    const int wm = (warp >> 2) * 64;
    const int wn = (warp & 3) * 32;
    const int m0 = blockIdx.y * 128;
    const int n0 = blockIdx.x * 128;

    // ldmatrix lane addressing (byte offsets within a tile)
    const uint32_t aOff =
        ((wm + (lane & 15)) * LDA + ((lane >> 4) << 3)) * 2;
    const uint32_t bOff =
        ((wn + (lane & 7) + (((lane >> 4) & 1) << 3)) * LDA + (((lane >> 3) & 1) << 3)) * 2;

    float acc[4][4][4] = {};

    const int NCHUNK = Kd >> 5;

    issue_chunk(s0, Ah, Al, Bh, Bl, m0, n0, M, Kd, 0, tid);
    CP_COMMIT();

    for (int c = 0; c < NCHUNK; c++) {
        const uint32_t sb = s0 + (c & 1) * BUF_BYTES;
        const bool has_next = (c + 1 < NCHUNK);
        if (has_next) {
            issue_chunk(s0 + ((c + 1) & 1) * BUF_BYTES, Ah, Al, Bh, Bl,
                        m0, n0, M, Kd, (c + 1) * 32, tid);
            CP_COMMIT();
            CP_WAIT1();
        } else {
            CP_WAIT0();
        }
        __syncthreads();

        const uint32_t sAh = sb, sAl = sb + TILE_BYTES;
        const uint32_t sBh = sb + 2 * TILE_BYTES, sBl = sb + 3 * TILE_BYTES;

#pragma unroll
        for (int k0 = 0; k0 < 32; k0 += 16) {
            uint32_t bh[4][2], bl[4][2];
#pragma unroll
            for (int np = 0; np < 2; np++) {
                uint32_t off = bOff + (np * 16 * LDA + k0) * 2;
                LDSM_X4(bh[2 * np][0], bh[2 * np][1],
                        bh[2 * np + 1][0], bh[2 * np + 1][1], sBh + off);
                LDSM_X4(bl[2 * np][0], bl[2 * np][1],
                        bl[2 * np + 1][0], bl[2 * np + 1][1], sBl + off);
            }
#pragma unroll
            for (int mt = 0; mt < 4; mt++) {
                uint32_t off = aOff + (mt * 16 * LDA + k0) * 2;
                uint32_t ah[4], al[4];
                LDSM_X4(ah[0], ah[1], ah[2], ah[3], sAh + off);
                LDSM_X4(al[0], al[1], al[2], al[3], sAl + off);
#pragma unroll
                for (int nt = 0; nt < 4; nt++) {
                    mma16816(acc[mt][nt], ah, bh[nt]);
                    mma16816(acc[mt][nt], ah, bl[nt]);
                    mma16816(acc[mt][nt], al, bh[nt]);
                }
            }
        }
        __syncthreads();
    }

    // Epilogue
#pragma unroll
    for (int mt = 0; mt < 4; mt++) {
        int m1 = m0 + wm + mt * 16 + gid;
        int m2 = m1 + 8;
        int b1i = 0, b2i = 0;
        if (ACT == 0) {
            b1i = (m1 < M) ? __ldg(&batch[m1]) : 0;
            b2i = (m2 < M) ? __ldg(&batch[m2]) : 0;
        }
#pragma unroll
        for (int nt = 0; nt < 4; nt++) {
            int n = n0 + wn + nt * 8 + 2 * tig;
            float2 bb = *(const float2*)(bias + n);
            float f0 = acc[mt][nt][0] + bb.x;
            float f1 = acc[mt][nt][1] + bb.y;
            float f2 = acc[mt][nt][2] + bb.x;
            float f3 = acc[mt][nt][3] + bb.y;
            if (ACT == 1) {
                f0 = f0 > 0.f ? f0 : 1.5f * f0;
                f1 = f1 > 0.f ? f1 : 1.5f * f1;
                f2 = f2 > 0.f ? f2 : 1.5f * f2;
                f3 = f3 > 0.f ? f3 : 1.5f * f3;
            } else if (ACT == 2) {
                f0 = fmaxf(f0, 0.f); f1 = fmaxf(f1, 0.f);
                f2 = fmaxf(f2, 0.f); f3 = fmaxf(f3, 0.f);
            }
            if (ACT == 0) {
                // fused global-mean-pool accumulation
                if (m1 < M) {
                    atomicAdd(&g_pool[b1i * DH + n], f0);
                    atomicAdd(&g_pool[b1i * DH + n + 1], f1);
                }
                if (m2 < M) {
                    atomicAdd(&g_pool[b2i * DH + n], f2);
                    atomicAdd(&g_pool[b2i * DH + n + 1], f3);
                }
            } else {
                if (m1 < M) {
                    __nv_bfloat16 h0 = __float2bfloat16(f0);
                    __nv_bfloat16 h1 = __float2bfloat16(f1);
                    __nv_bfloat162 hp; hp.x = h0; hp.y = h1;
                    __nv_bfloat162 lp;
                    lp.x = __float2bfloat16(f0 - __bfloat162float(h0));
                    lp.y = __float2bfloat16(f1 - __bfloat162float(h1));
                    *(__nv_bfloat162*)(Oh + (size_t)m1 * DH + n) = hp;
                    *(__nv_bfloat162*)(Ol + (size_t)m1 * DH + n) = lp;
                }
                if (m2 < M) {
                    __nv_bfloat16 h2 = __float2bfloat16(f2);
                    __nv_bfloat16 h3 = __float2bfloat16(f3);
                    __nv_bfloat162 hp; hp.x = h2; hp.y = h3;
                    __nv_bfloat162 lp;
                    lp.x = __float2bfloat16(f2 - __bfloat162float(h2));
                    lp.y = __float2bfloat16(f3 - __bfloat162float(h3));
                    *(__nv_bfloat162*)(Oh + (size_t)m2 * DH + n) = hp;
                    *(__nv_bfloat162*)(Ol + (size_t)m2 * DH + n) = lp;
                }
            }
        }
    }
}

// ---------------------------------------------------------------------------
__global__ void zero_pool_kernel() {
    int i = blockIdx.x * blockDim.x + threadIdx.x;
    if (i < GG * DH) g_pool[i] = 0.f;
    if (i < GG) g_cnt[i] = 0.f;
}

__global__ void count_kernel(const int* __restrict__ batch) {
    int i = blockIdx.x * blockDim.x + threadIdx.x;
    if (i < NN) atomicAdd(&g_cnt[__ldg(&batch[i])], 1.0f);
}

__global__ void final_out_kernel(const float* __restrict__ Wl,
                                 const float* __restrict__ bl,
                                 float* __restrict__ out) {
    __shared__ float p[DH];
    __shared__ float red[DOUT];
    int g = blockIdx.x;
    int t = threadIdx.x;

    float inv_cnt = 1.0f / fmaxf(g_cnt[g], 1.0f);
    for (int k = t; k < DH; k += DOUT)
        p[k] = g_pool[g * DH + k] * inv_cnt;
    __syncthreads();

    float acc = bl[t];
#pragma unroll 8
    for (int k = 0; k < DH; k++)
        acc += p[k] * Wl[k * DOUT + t];

    red[t] = acc * acc;
    __syncthreads();
    for (int s = DOUT / 2; s > 0; s >>= 1) {
        if (t < s) red[t] += red[t + s];
        __syncthreads();
    }
    float nrm = fmaxf(sqrtf(red[0]), 1e-12f);
    out[g * DOUT + t] = acc / nrm;
}

// ---------------------------------------------------------------------------
extern "C" void kernel_launch(void* const* d_in, const int* in_sizes, int n_in,
                              void* d_out, int out_size) {
    const float* x     = (const float*)d_in[0];
    const int*   ei    = (const int*)d_in[1];
    const int*   batch = (const int*)d_in[2];
    const float* W1 = (const float*)d_in[3];
    const float* b1 = (const float*)d_in[4];
    const float* W2 = (const float*)d_in[5];
    const float* b2 = (const float*)d_in[6];
    const float* W3 = (const float*)d_in[7];
    const float* b3 = (const float*)d_in[8];
    const float* W4 = (const float*)d_in[9];
    const float* b4 = (const float*)d_in[10];
    const float* Wl = (const float*)d_in[11];
    const float* bl = (const float*)d_in[12];
    float* out = (float*)d_out;

    __nv_bfloat16 *a0h, *a0l, *a1h, *a1l;
    __nv_bfloat16 *w1h, *w1l, *w2h, *w2l, *w3h, *w3l, *w4h, *w4l;
    cudaGetSymbolAddress((void**)&a0h, g_a0h);
    cudaGetSymbolAddress((void**)&a0l, g_a0l);
    cudaGetSymbolAddress((void**)&a1h, g_a1h);
    cudaGetSymbolAddress((void**)&a1l, g_a1l);
    cudaGetSymbolAddress((void**)&w1h, g_w1h);
    cudaGetSymbolAddress((void**)&w1l, g_w1l);
    cudaGetSymbolAddress((void**)&w2h, g_w2h);
    cudaGetSymbolAddress((void**)&w2l, g_w2l);
    cudaGetSymbolAddress((void**)&w3h, g_w3h);
    cudaGetSymbolAddress((void**)&w3l, g_w3l);
    cudaGetSymbolAddress((void**)&w4h, g_w4h);
    cudaGetSymbolAddress((void**)&w4l, g_w4l);

    cudaFuncSetAttribute(gemm_mma_kernel<0>, cudaFuncAttributeMaxDynamicSharedMemorySize, GEMM_SMEM);
    cudaFuncSetAttribute(gemm_mma_kernel<1>, cudaFuncAttributeMaxDynamicSharedMemorySize, GEMM_SMEM);
    cudaFuncSetAttribute(gemm_mma_kernel<2>, cudaFuncAttributeMaxDynamicSharedMemorySize, GEMM_SMEM);

    // 1) aggregation + input split
    copy_x_kernel<<<(NN * DIN / 4 + 255) / 256, 256>>>(x);
    edge_agg_kernel<<<(int)(((long long)EE * 32 + 255) / 256), 256>>>(x, ei);
    split_x_kernel<<<(NN * DIN + 255) / 256, 256>>>();

    // 2) weight transpose + split; pool init + counts (needed before layer 4)
    splitW_kernel<<<(512 * DIN + 255) / 256, 256>>>(W1, DIN, w1h, w1l);
    splitW_kernel<<<(512 * DH + 255) / 256, 256>>>(W2, DH, w2h, w2l);
    splitW_kernel<<<(512 * DH + 255) / 256, 256>>>(W3, DH, w3h, w3l);
    splitW_kernel<<<(512 * DH + 255) / 256, 256>>>(W4, DH, w4h, w4l);
    zero_pool_kernel<<<(GG * DH + 255) / 256, 256>>>();
    count_kernel<<<(NN + 255) / 256, 256>>>(batch);

    // 3) 4-layer MLP (mma.sync bf16 3-pass); layer 4 fuses mean-pool atomics
    dim3 grid(DH / 128, (NN + 127) / 128);
    gemm_mma_kernel<1><<<grid, 256, GEMM_SMEM>>>(a0h, a0l, w1h, w1l, b1, a1h, a1l, nullptr, NN, DIN);
    gemm_mma_kernel<2><<<grid, 256, GEMM_SMEM>>>(a1h, a1l, w2h, w2l, b2, a0h, a0l, nullptr, NN, DH);
    gemm_mma_kernel<2><<<grid, 256, GEMM_SMEM>>>(a0h, a0l, w3h, w3l, b3, a1h, a1l, nullptr, NN, DH);
    gemm_mma_kernel<0><<<grid, 256, GEMM_SMEM>>>(a1h, a1l, w4h, w4l, b4, nullptr, nullptr, batch, NN, DH);

    // 4) final linear + L2 normalize
    final_out_kernel<<<GG, DOUT>>>(Wl, bl, out);
}

// round 8
// speedup vs baseline: 2.9447x; 1.1554x over previous
#include <cuda_runtime.h>
#include <cuda_bf16.h>
#include <cstdint>

#define NN   50000
#define EE   800000
#define DIN  128
#define DH   512
#define DOUT 256
#define GG   512

// ---------------------------------------------------------------------------
__device__ __align__(16) float g_h0[NN * DIN];
__device__ __align__(16) float g_pool[GG * DH];
__device__ float g_cnt[GG];

__device__ __align__(16) __nv_bfloat16 g_a0h[NN * DH];
__device__ __align__(16) __nv_bfloat16 g_a0l[NN * DH];
__device__ __align__(16) __nv_bfloat16 g_a1h[NN * DH];
__device__ __align__(16) __nv_bfloat16 g_a1l[NN * DH];

__device__ __align__(16) __nv_bfloat16 g_w1h[DH * DIN], g_w1l[DH * DIN];
__device__ __align__(16) __nv_bfloat16 g_w2h[DH * DH],  g_w2l[DH * DH];
__device__ __align__(16) __nv_bfloat16 g_w3h[DH * DH],  g_w3l[DH * DH];
__device__ __align__(16) __nv_bfloat16 g_w4h[DH * DH],  g_w4l[DH * DH];

// ---------------------------------------------------------------------------
__device__ __forceinline__ uint32_t smem_u32(const void* p) {
    uint32_t a;
    asm("{ .reg .u64 t; cvta.to.shared.u64 t, %1; cvt.u32.u64 %0, t; }"
        : "=r"(a) : "l"(p));
    return a;
}
#define CP16(dst, src) \
    asm volatile("cp.async.cg.shared.global [%0], [%1], 16;" :: "r"(dst), "l"(src))
#define CP_COMMIT() asm volatile("cp.async.commit_group;" ::: "memory")
#define CP_WAIT0()  asm volatile("cp.async.wait_group 0;" ::: "memory")
#define CP_WAIT1()  asm volatile("cp.async.wait_group 1;" ::: "memory")
#define LDSM_X4(r0, r1, r2, r3, addr) \
    asm volatile("ldmatrix.sync.aligned.m8n8.x4.shared.b16 {%0,%1,%2,%3}, [%4];" \
                 : "=r"(r0), "=r"(r1), "=r"(r2), "=r"(r3) : "r"(addr))

__device__ __forceinline__ void red_v4(float* p, float4 v) {
    asm volatile("red.global.add.v4.f32 [%0], {%1,%2,%3,%4};"
                 :: "l"(p), "f"(v.x), "f"(v.y), "f"(v.z), "f"(v.w) : "memory");
}
__device__ __forceinline__ void red_v2(float* p, float a, float b) {
    asm volatile("red.global.add.v2.f32 [%0], {%1,%2};"
                 :: "l"(p), "f"(a), "f"(b) : "memory");
}

__device__ __forceinline__ void mma16816(float* d, const uint32_t* a,
                                         const uint32_t* b) {
    asm volatile(
        "mma.sync.aligned.m16n8k16.row.col.f32.bf16.bf16.f32 "
        "{%0,%1,%2,%3}, {%4,%5,%6,%7}, {%8,%9}, {%0,%1,%2,%3};"
        : "+f"(d[0]), "+f"(d[1]), "+f"(d[2]), "+f"(d[3])
        : "r"(a[0]), "r"(a[1]), "r"(a[2]), "r"(a[3]), "r"(b[0]), "r"(b[1]));
}

// ---------------------------------------------------------------------------
__global__ void copy_x_kernel(const float* __restrict__ x) {
    int i = blockIdx.x * blockDim.x + threadIdx.x;
    if (i < NN * DIN / 4) ((float4*)g_h0)[i] = ((const float4*)x)[i];
}

// h0[dst] += x[src], one red.v4 per 16B chunk
__global__ void edge_agg_kernel(const float* __restrict__ x,
                                const int* __restrict__ ei) {
    long long idx = (long long)blockIdx.x * blockDim.x + threadIdx.x;
    if (idx >= (long long)EE * (DIN / 4)) return;
    int e = (int)(idx >> 5);
    int c = ((int)idx & 31) * 4;
    int src = __ldg(&ei[e]);
    int dst = __ldg(&ei[EE + e]);
    float4 v = *(const float4*)(x + (size_t)src * DIN + c);
    red_v4(g_h0 + (size_t)dst * DIN + c, v);
}

// fp32 -> (bf16 hi, bf16 lo), vectorized
__global__ void split_x_kernel() {
    int i = blockIdx.x * blockDim.x + threadIdx.x;
    if (i >= NN * DIN / 4) return;
    float4 f = ((const float4*)g_h0)[i];
    __nv_bfloat162 h01, h23, l01, l23;
    h01.x = __float2bfloat16(f.x); h01.y = __float2bfloat16(f.y);
    h23.x = __float2bfloat16(f.z); h23.y = __float2bfloat16(f.w);
    l01.x = __float2bfloat16(f.x - __bfloat162float(h01.x));
    l01.y = __float2bfloat16(f.y - __bfloat162float(h01.y));
    l23.x = __float2bfloat16(f.z - __bfloat162float(h23.x));
    l23.y = __float2bfloat16(f.w - __bfloat162float(h23.y));
    ((__nv_bfloat162*)g_a0h)[2 * i] = h01;
    ((__nv_bfloat162*)g_a0h)[2 * i + 1] = h23;
    ((__nv_bfloat162*)g_a0l)[2 * i] = l01;
    ((__nv_bfloat162*)g_a0l)[2 * i + 1] = l23;
}

__global__ void splitW_kernel(const float* __restrict__ W, int Kd,
                              __nv_bfloat16* __restrict__ oh,
                              __nv_bfloat16* __restrict__ ol) {
    int i = blockIdx.x * blockDim.x + threadIdx.x;
    if (i >= 512 * Kd) return;
    int n = i / Kd;
    int k = i - n * Kd;
    float f = W[(size_t)k * 512 + n];
    __nv_bfloat16 h = __float2bfloat16(f);
    __nv_bfloat16 l = __float2bfloat16(f - __bfloat162float(h));
    oh[i] = h;
    ol[i] = l;
}

// ---------------------------------------------------------------------------
#define LDA         40
#define TILE_BYTES  (128 * LDA * 2)
#define BUF_BYTES   (4 * TILE_BYTES)
#define GEMM_SMEM   (2 * BUF_BYTES)

__device__ __forceinline__ void issue_chunk(uint32_t sb,
                                            const __nv_bfloat16* __restrict__ Ah,
                                            const __nv_bfloat16* __restrict__ Al,
                                            const __nv_bfloat16* __restrict__ Bh,
                                            const __nv_bfloat16* __restrict__ Bl,
                                            int m0, int n0, int M, int Kd, int kb,
                                            int tid) {
#pragma unroll
    for (int j = 0; j < 2; j++) {
        int idx = tid + 256 * j;
        int row = idx >> 2;
        int seg = idx & 3;
        uint32_t doff = row * (LDA * 2) + seg * 16;
        int ar = m0 + row;
        if (ar >= M) ar = M - 1;
        int br = n0 + row;
        size_t ko = (size_t)kb + seg * 8;
        CP16(sb + 0 * TILE_BYTES + doff, Ah + (size_t)ar * Kd + ko);
        CP16(sb + 1 * TILE_BYTES + doff, Al + (size_t)ar * Kd + ko);
        CP16(sb + 2 * TILE_BYTES + doff, Bh + (size_t)br * Kd + ko);
        CP16(sb + 3 * TILE_BYTES + doff, Bl + (size_t)br * Kd + ko);
    }
}

// ACT: 0 -> fused mean-pool red.v2; 1 -> LeakyReLU(1.5) split; 2 -> ReLU split.
template <int ACT>
__global__ __launch_bounds__(256, 2)
void gemm_mma_kernel(const __nv_bfloat16* __restrict__ Ah,
                     const __nv_bfloat16* __restrict__ Al,
                     const __nv_bfloat16* __restrict__ Bh,
                     const __nv_bfloat16* __restrict__ Bl,
                     const float* __restrict__ bias,
                     __nv_bfloat16* __restrict__ Oh,
                     __nv_bfloat16* __restrict__ Ol,
                     const int* __restrict__ batch,
                     int M, int Kd) {
    extern __shared__ char smem[];
    const uint32_t s0 = smem_u32(smem);

    const int tid  = threadIdx.x;
    const int warp = tid >> 5;
    const int lane = tid & 31;
    const int gid  = lane >> 2;
    const int tig  = lane & 3;
    const int wm = (warp >> 2) * 64;
    const int wn = (warp & 3) * 32;
    const int m0 = blockIdx.y * 128;
    const int n0 = blockIdx.x * 128;

    const uint32_t aOff =
        ((wm + (lane & 15)) * LDA + ((lane >> 4) << 3)) * 2;
    const uint32_t bOff =
        ((wn + (lane & 7) + (((lane >> 4) & 1) << 3)) * LDA + (((lane >> 3) & 1) << 3)) * 2;

    float acc[4][4][4] = {};

    const int NCHUNK = Kd >> 5;

    issue_chunk(s0, Ah, Al, Bh, Bl, m0, n0, M, Kd, 0, tid);
    CP_COMMIT();

    for (int c = 0; c < NCHUNK; c++) {
        const uint32_t sb = s0 + (c & 1) * BUF_BYTES;
        const bool has_next = (c + 1 < NCHUNK);
        if (has_next) {
            issue_chunk(s0 + ((c + 1) & 1) * BUF_BYTES, Ah, Al, Bh, Bl,
                        m0, n0, M, Kd, (c + 1) * 32, tid);
            CP_COMMIT();
            CP_WAIT1();
        } else {
            CP_WAIT0();
        }
        __syncthreads();

        const uint32_t sAh = sb, sAl = sb + TILE_BYTES;
        const uint32_t sBh = sb + 2 * TILE_BYTES, sBl = sb + 3 * TILE_BYTES;

#pragma unroll
        for (int k0 = 0; k0 < 32; k0 += 16) {
            uint32_t bh[4][2], bl[4][2];
#pragma unroll
            for (int np = 0; np < 2; np++) {
                uint32_t off = bOff + (np * 16 * LDA + k0) * 2;
                LDSM_X4(bh[2 * np][0], bh[2 * np][1],
                        bh[2 * np + 1][0], bh[2 * np + 1][1], sBh + off);
                LDSM_X4(bl[2 * np][0], bl[2 * np][1],
                        bl[2 * np + 1][0], bl[2 * np + 1][1], sBl + off);
            }
#pragma unroll
            for (int mt = 0; mt < 4; mt++) {
                uint32_t off = aOff + (mt * 16 * LDA + k0) * 2;
                uint32_t ah[4], al[4];
                LDSM_X4(ah[0], ah[1], ah[2], ah[3], sAh + off);
                LDSM_X4(al[0], al[1], al[2], al[3], sAl + off);
#pragma unroll
                for (int nt = 0; nt < 4; nt++) {
                    mma16816(acc[mt][nt], ah, bh[nt]);
                    mma16816(acc[mt][nt], ah, bl[nt]);
                    mma16816(acc[mt][nt], al, bh[nt]);
                }
            }
        }
        __syncthreads();
    }

    // Epilogue
#pragma unroll
    for (int mt = 0; mt < 4; mt++) {
        int m1 = m0 + wm + mt * 16 + gid;
        int m2 = m1 + 8;
        int b1i = 0, b2i = 0;
        if (ACT == 0) {
            b1i = (m1 < M) ? __ldg(&batch[m1]) : 0;
            b2i = (m2 < M) ? __ldg(&batch[m2]) : 0;
        }
#pragma unroll
        for (int nt = 0; nt < 4; nt++) {
            int n = n0 + wn + nt * 8 + 2 * tig;
            float2 bb = *(const float2*)(bias + n);
            float f0 = acc[mt][nt][0] + bb.x;
            float f1 = acc[mt][nt][1] + bb.y;
            float f2 = acc[mt][nt][2] + bb.x;
            float f3 = acc[mt][nt][3] + bb.y;
            if (ACT == 1) {
                f0 = f0 > 0.f ? f0 : 1.5f * f0;
                f1 = f1 > 0.f ? f1 : 1.5f * f1;
                f2 = f2 > 0.f ? f2 : 1.5f * f2;
                f3 = f3 > 0.f ? f3 : 1.5f * f3;
            } else if (ACT == 2) {
                f0 = fmaxf(f0, 0.f); f1 = fmaxf(f1, 0.f);
                f2 = fmaxf(f2, 0.f); f3 = fmaxf(f3, 0.f);
            }
            if (ACT == 0) {
                if (m1 < M) red_v2(&g_pool[b1i * DH + n], f0, f1);
                if (m2 < M) red_v2(&g_pool[b2i * DH + n], f2, f3);
            } else {
                if (m1 < M) {
                    __nv_bfloat16 h0 = __float2bfloat16(f0);
                    __nv_bfloat16 h1 = __float2bfloat16(f1);
                    __nv_bfloat162 hp; hp.x = h0; hp.y = h1;
                    __nv_bfloat162 lp;
                    lp.x = __float2bfloat16(f0 - __bfloat162float(h0));
                    lp.y = __float2bfloat16(f1 - __bfloat162float(h1));
                    *(__nv_bfloat162*)(Oh + (size_t)m1 * DH + n) = hp;
                    *(__nv_bfloat162*)(Ol + (size_t)m1 * DH + n) = lp;
                }
                if (m2 < M) {
                    __nv_bfloat16 h2 = __float2bfloat16(f2);
                    __nv_bfloat16 h3 = __float2bfloat16(f3);
                    __nv_bfloat162 hp; hp.x = h2; hp.y = h3;
                    __nv_bfloat162 lp;
                    lp.x = __float2bfloat16(f2 - __bfloat162float(h2));
                    lp.y = __float2bfloat16(f3 - __bfloat162float(h3));
                    *(__nv_bfloat162*)(Oh + (size_t)m2 * DH + n) = hp;
                    *(__nv_bfloat162*)(Ol + (size_t)m2 * DH + n) = lp;
                }
            }
        }
    }
}

// ---------------------------------------------------------------------------
__global__ void zero_pool_kernel() {
    int i = blockIdx.x * blockDim.x + threadIdx.x;
    if (i < GG * DH) g_pool[i] = 0.f;
    if (i < GG) g_cnt[i] = 0.f;
}

__global__ void count_kernel(const int* __restrict__ batch) {
    int i = blockIdx.x * blockDim.x + threadIdx.x;
    if (i < NN) atomicAdd(&g_cnt[__ldg(&batch[i])], 1.0f);
}

__global__ void final_out_kernel(const float* __restrict__ Wl,
                                 const float* __restrict__ bl,
                                 float* __restrict__ out) {
    __shared__ float p[DH];
    __shared__ float red[DOUT];
    int g = blockIdx.x;
    int t = threadIdx.x;

    float inv_cnt = 1.0f / fmaxf(g_cnt[g], 1.0f);
    for (int k = t; k < DH; k += DOUT)
        p[k] = g_pool[g * DH + k] * inv_cnt;
    __syncthreads();

    float acc = bl[t];
#pragma unroll 8
    for (int k = 0; k < DH; k++)
        acc += p[k] * Wl[k * DOUT + t];

    red[t] = acc * acc;
    __syncthreads();
    for (int s = DOUT / 2; s > 0; s >>= 1) {
        if (t < s) red[t] += red[t + s];
        __syncthreads();
    }
    float nrm = fmaxf(sqrtf(red[0]), 1e-12f);
    out[g * DOUT + t] = acc / nrm;
}

// ---------------------------------------------------------------------------
extern "C" void kernel_launch(void* const* d_in, const int* in_sizes, int n_in,
                              void* d_out, int out_size) {
    const float* x     = (const float*)d_in[0];
    const int*   ei    = (const int*)d_in[1];
    const int*   batch = (const int*)d_in[2];
    const float* W1 = (const float*)d_in[3];
    const float* b1 = (const float*)d_in[4];
    const float* W2 = (const float*)d_in[5];
    const float* b2 = (const float*)d_in[6];
    const float* W3 = (const float*)d_in[7];
    const float* b3 = (const float*)d_in[8];
    const float* W4 = (const float*)d_in[9];
    const float* b4 = (const float*)d_in[10];
    const float* Wl = (const float*)d_in[11];
    const float* bl = (const float*)d_in[12];
    float* out = (float*)d_out;

    __nv_bfloat16 *a0h, *a0l, *a1h, *a1l;
    __nv_bfloat16 *w1h, *w1l, *w2h, *w2l, *w3h, *w3l, *w4h, *w4l;
    cudaGetSymbolAddress((void**)&a0h, g_a0h);
    cudaGetSymbolAddress((void**)&a0l, g_a0l);
    cudaGetSymbolAddress((void**)&a1h, g_a1h);
    cudaGetSymbolAddress((void**)&a1l, g_a1l);
    cudaGetSymbolAddress((void**)&w1h, g_w1h);
    cudaGetSymbolAddress((void**)&w1l, g_w1l);
    cudaGetSymbolAddress((void**)&w2h, g_w2h);
    cudaGetSymbolAddress((void**)&w2l, g_w2l);
    cudaGetSymbolAddress((void**)&w3h, g_w3h);
    cudaGetSymbolAddress((void**)&w3l, g_w3l);
    cudaGetSymbolAddress((void**)&w4h, g_w4h);
    cudaGetSymbolAddress((void**)&w4l, g_w4l);

    cudaFuncSetAttribute(gemm_mma_kernel<0>, cudaFuncAttributeMaxDynamicSharedMemorySize, GEMM_SMEM);
    cudaFuncSetAttribute(gemm_mma_kernel<1>, cudaFuncAttributeMaxDynamicSharedMemorySize, GEMM_SMEM);
    cudaFuncSetAttribute(gemm_mma_kernel<2>, cudaFuncAttributeMaxDynamicSharedMemorySize, GEMM_SMEM);

    // 1) aggregation + input split
    copy_x_kernel<<<(NN * DIN / 4 + 255) / 256, 256>>>(x);
    edge_agg_kernel<<<(int)(((long long)EE * 32 + 255) / 256), 256>>>(x, ei);
    split_x_kernel<<<(NN * DIN / 4 + 255) / 256, 256>>>();

    // 2) weight transpose + split; pool init + counts
    splitW_kernel<<<(512 * DIN + 255) / 256, 256>>>(W1, DIN, w1h, w1l);
    splitW_kernel<<<(512 * DH + 255) / 256, 256>>>(W2, DH, w2h, w2l);
    splitW_kernel<<<(512 * DH + 255) / 256, 256>>>(W3, DH, w3h, w3l);
    splitW_kernel<<<(512 * DH + 255) / 256, 256>>>(W4, DH, w4h, w4l);
    zero_pool_kernel<<<(GG * DH + 255) / 256, 256>>>();
    count_kernel<<<(NN + 255) / 256, 256>>>(batch);

    // 3) 4-layer MLP; layer 4 fuses mean-pool red.v2
    dim3 grid(DH / 128, (NN + 127) / 128);
    gemm_mma_kernel<1><<<grid, 256, GEMM_SMEM>>>(a0h, a0l, w1h, w1l, b1, a1h, a1l, nullptr, NN, DIN);
    gemm_mma_kernel<2><<<grid, 256, GEMM_SMEM>>>(a1h, a1l, w2h, w2l, b2, a0h, a0l, nullptr, NN, DH);
    gemm_mma_kernel<2><<<grid, 256, GEMM_SMEM>>>(a0h, a0l, w3h, w3l, b3, a1h, a1l, nullptr, NN, DH);
    gemm_mma_kernel<0><<<grid, 256, GEMM_SMEM>>>(a1h, a1l, w4h, w4l, b4, nullptr, nullptr, batch, NN, DH);

    // 4) final linear + L2 normalize
    final_out_kernel<<<GG, DOUT>>>(Wl, bl, out);
}

// round 9
// speedup vs baseline: 3.1135x; 1.0573x over previous
#include <cuda_runtime.h>
#include <cuda_bf16.h>
#include <cstdint>

#define NN   50000
#define EE   800000
#define DIN  128
#define DH   512
#define DOUT 256
#define GG   512
#define NBLK 196                      // ceil(NN/256)

// ---------------------------------------------------------------------------
__device__ __align__(16) float g_pool[GG * DH];
__device__ float g_cnt[GG];

// CSR scratch
__device__ int g_deg[NN];
__device__ int g_fill[NN];
__device__ int g_offs[NN];            // exclusive scan within 256-block
__device__ int g_bsum[256];           // per-block totals -> exclusive base
__device__ int g_eidx[EE];

// Activation ping-pong, bf16 hi/lo split
__device__ __align__(16) __nv_bfloat16 g_a0h[NN * DH];
__device__ __align__(16) __nv_bfloat16 g_a0l[NN * DH];
__device__ __align__(16) __nv_bfloat16 g_a1h[NN * DH];
__device__ __align__(16) __nv_bfloat16 g_a1l[NN * DH];

// Weights, transposed to [n][k] and split hi/lo
__device__ __align__(16) __nv_bfloat16 g_w1h[DH * DIN], g_w1l[DH * DIN];
__device__ __align__(16) __nv_bfloat16 g_w2h[DH * DH],  g_w2l[DH * DH];
__device__ __align__(16) __nv_bfloat16 g_w3h[DH * DH],  g_w3l[DH * DH];
__device__ __align__(16) __nv_bfloat16 g_w4h[DH * DH],  g_w4l[DH * DH];

// ---------------------------------------------------------------------------
__device__ __forceinline__ uint32_t smem_u32(const void* p) {
    uint32_t a;
    asm("{ .reg .u64 t; cvta.to.shared.u64 t, %1; cvt.u32.u64 %0, t; }"
        : "=r"(a) : "l"(p));
    return a;
}
#define CP16(dst, src) \
    asm volatile("cp.async.cg.shared.global [%0], [%1], 16;" :: "r"(dst), "l"(src))
#define CP_COMMIT() asm volatile("cp.async.commit_group;" ::: "memory")
#define CP_WAIT0()  asm volatile("cp.async.wait_group 0;" ::: "memory")
#define CP_WAIT1()  asm volatile("cp.async.wait_group 1;" ::: "memory")
#define LDSM_X4(r0, r1, r2, r3, addr) \
    asm volatile("ldmatrix.sync.aligned.m8n8.x4.shared.b16 {%0,%1,%2,%3}, [%4];" \
                 : "=r"(r0), "=r"(r1), "=r"(r2), "=r"(r3) : "r"(addr))

__device__ __forceinline__ void red_v2(float* p, float a, float b) {
    asm volatile("red.global.add.v2.f32 [%0], {%1,%2};"
                 :: "l"(p), "f"(a), "f"(b) : "memory");
}

__device__ __forceinline__ void mma16816(float* d, const uint32_t* a,
                                         const uint32_t* b) {
    asm volatile(
        "mma.sync.aligned.m16n8k16.row.col.f32.bf16.bf16.f32 "
        "{%0,%1,%2,%3}, {%4,%5,%6,%7}, {%8,%9}, {%0,%1,%2,%3};"
        : "+f"(d[0]), "+f"(d[1]), "+f"(d[2]), "+f"(d[3])
        : "r"(a[0]), "r"(a[1]), "r"(a[2]), "r"(a[3]), "r"(b[0]), "r"(b[1]));
}

// ---------------------------------------------------------------------------
// CSR build
__global__ void zero_deg_kernel() {
    int i = blockIdx.x * blockDim.x + threadIdx.x;
    if (i < NN) { g_deg[i] = 0; g_fill[i] = 0; }
}

__global__ void hist_kernel(const int* __restrict__ ei) {
    int i = blockIdx.x * blockDim.x + threadIdx.x;
    if (i < EE) atomicAdd(&g_deg[__ldg(&ei[EE + i])], 1);
}

// per-256-block inclusive scan -> exclusive offsets + block totals
__global__ void scan1_kernel() {
    __shared__ int s[256];
    int tid = threadIdx.x;
    int idx = blockIdx.x * 256 + tid;
    int v = (idx < NN) ? g_deg[idx] : 0;
    s[tid] = v;
    __syncthreads();
#pragma unroll
    for (int d = 1; d < 256; d <<= 1) {
        int t = (tid >= d) ? s[tid - d] : 0;
        __syncthreads();
        s[tid] += t;
        __syncthreads();
    }
    if (idx < NN) g_offs[idx] = s[tid] - v;
    if (tid == 255) g_bsum[blockIdx.x] = s[255];
}

// exclusive scan of block totals (one block)
__global__ void scan2_kernel() {
    __shared__ int s[256];
    int tid = threadIdx.x;
    int v = (tid < NBLK) ? g_bsum[tid] : 0;
    s[tid] = v;
    __syncthreads();
#pragma unroll
    for (int d = 1; d < 256; d <<= 1) {
        int t = (tid >= d) ? s[tid - d] : 0;
        __syncthreads();
        s[tid] += t;
        __syncthreads();
    }
    g_bsum[tid] = s[tid] - v;   // exclusive base
}

__global__ void scatter_kernel(const int* __restrict__ ei) {
    int e = blockIdx.x * blockDim.x + threadIdx.x;
    if (e >= EE) return;
    int src = __ldg(&ei[e]);
    int dst = __ldg(&ei[EE + e]);
    int pos = g_offs[dst] + g_bsum[dst >> 8] + atomicAdd(&g_fill[dst], 1);
    g_eidx[pos] = src;
}

// warp-per-node: acc = x[n] + sum_{j} x[eidx[j]]; emit bf16 hi/lo directly
__global__ void csr_agg_kernel(const float* __restrict__ x) {
    int n = (blockIdx.x * blockDim.x + threadIdx.x) >> 5;
    if (n >= NN) return;
    int lane = threadIdx.x & 31;
    int base = g_offs[n] + g_bsum[n >> 8];
    int deg = g_deg[n];
    const float4* xr = (const float4*)x;

    float4 acc = __ldg(&xr[(size_t)n * 32 + lane]);
#pragma unroll 4
    for (int j = 0; j < deg; j++) {
        int s = __ldg(&g_eidx[base + j]);
        float4 v = __ldg(&xr[(size_t)s * 32 + lane]);
        acc.x += v.x; acc.y += v.y; acc.z += v.z; acc.w += v.w;
    }

    __nv_bfloat162 h01, h23, l01, l23;
    h01.x = __float2bfloat16(acc.x); h01.y = __float2bfloat16(acc.y);
    h23.x = __float2bfloat16(acc.z); h23.y = __float2bfloat16(acc.w);
    l01.x = __float2bfloat16(acc.x - __bfloat162float(h01.x));
    l01.y = __float2bfloat16(acc.y - __bfloat162float(h01.y));
    l23.x = __float2bfloat16(acc.z - __bfloat162float(h23.x));
    l23.y = __float2bfloat16(acc.w - __bfloat162float(h23.y));
    uint2 hv = make_uint2(*(uint32_t*)&h01, *(uint32_t*)&h23);
    uint2 lv = make_uint2(*(uint32_t*)&l01, *(uint32_t*)&l23);
    ((uint2*)(g_a0h + (size_t)n * DIN))[lane] = hv;
    ((uint2*)(g_a0l + (size_t)n * DIN))[lane] = lv;
}

// ---------------------------------------------------------------------------
__global__ void splitW_kernel(const float* __restrict__ W, int Kd,
                              __nv_bfloat16* __restrict__ oh,
                              __nv_bfloat16* __restrict__ ol) {
    int i = blockIdx.x * blockDim.x + threadIdx.x;
    if (i >= 512 * Kd) return;
    int n = i / Kd;
    int k = i - n * Kd;
    float f = W[(size_t)k * 512 + n];
    __nv_bfloat16 h = __float2bfloat16(f);
    __nv_bfloat16 l = __float2bfloat16(f - __bfloat162float(h));
    oh[i] = h;
    ol[i] = l;
}

// ---------------------------------------------------------------------------
#define LDA         40
#define TILE_BYTES  (128 * LDA * 2)
#define BUF_BYTES   (4 * TILE_BYTES)
#define GEMM_SMEM   (2 * BUF_BYTES)

__device__ __forceinline__ void issue_chunk(uint32_t sb,
                                            const __nv_bfloat16* __restrict__ Ah,
                                            const __nv_bfloat16* __restrict__ Al,
                                            const __nv_bfloat16* __restrict__ Bh,
                                            const __nv_bfloat16* __restrict__ Bl,
                                            int m0, int n0, int M, int Kd, int kb,
                                            int tid) {
#pragma unroll
    for (int j = 0; j < 2; j++) {
        int idx = tid + 256 * j;
        int row = idx >> 2;
        int seg = idx & 3;
        uint32_t doff = row * (LDA * 2) + seg * 16;
        int ar = m0 + row;
        if (ar >= M) ar = M - 1;
        int br = n0 + row;
        size_t ko = (size_t)kb + seg * 8;
        CP16(sb + 0 * TILE_BYTES + doff, Ah + (size_t)ar * Kd + ko);
        CP16(sb + 1 * TILE_BYTES + doff, Al + (size_t)ar * Kd + ko);
        CP16(sb + 2 * TILE_BYTES + doff, Bh + (size_t)br * Kd + ko);
        CP16(sb + 3 * TILE_BYTES + doff, Bl + (size_t)br * Kd + ko);
    }
}

// ACT: 0 -> fused mean-pool red.v2; 1 -> LeakyReLU(1.5) split; 2 -> ReLU split.
template <int ACT>
__global__ __launch_bounds__(256, 2)
void gemm_mma_kernel(const __nv_bfloat16* __restrict__ Ah,
                     const __nv_bfloat16* __restrict__ Al,
                     const __nv_bfloat16* __restrict__ Bh,
                     const __nv_bfloat16* __restrict__ Bl,
                     const float* __restrict__ bias,
                     __nv_bfloat16* __restrict__ Oh,
                     __nv_bfloat16* __restrict__ Ol,
                     const int* __restrict__ batch,
                     int M, int Kd) {
    extern __shared__ char smem[];
    const uint32_t s0 = smem_u32(smem);

    const int tid  = threadIdx.x;
    const int warp = tid >> 5;
    const int lane = tid & 31;
    const int gid  = lane >> 2;
    const int tig  = lane & 3;
    const int wm = (warp >> 2) * 64;
    const int wn = (warp & 3) * 32;
    const int m0 = blockIdx.y * 128;
    const int n0 = blockIdx.x * 128;

    const uint32_t aOff =
        ((wm + (lane & 15)) * LDA + ((lane >> 4) << 3)) * 2;
    const uint32_t bOff =
        ((wn + (lane & 7) + (((lane >> 4) & 1) << 3)) * LDA + (((lane >> 3) & 1) << 3)) * 2;

    float acc[4][4][4] = {};

    const int NCHUNK = Kd >> 5;

    issue_chunk(s0, Ah, Al, Bh, Bl, m0, n0, M, Kd, 0, tid);
    CP_COMMIT();

    for (int c = 0; c < NCHUNK; c++) {
        const uint32_t sb = s0 + (c & 1) * BUF_BYTES;
        const bool has_next = (c + 1 < NCHUNK);
        if (has_next) {
            issue_chunk(s0 + ((c + 1) & 1) * BUF_BYTES, Ah, Al, Bh, Bl,
                        m0, n0, M, Kd, (c + 1) * 32, tid);
            CP_COMMIT();
            CP_WAIT1();
        } else {
            CP_WAIT0();
        }
        __syncthreads();

        const uint32_t sAh = sb, sAl = sb + TILE_BYTES;
        const uint32_t sBh = sb + 2 * TILE_BYTES, sBl = sb + 3 * TILE_BYTES;

#pragma unroll
        for (int k0 = 0; k0 < 32; k0 += 16) {
            uint32_t bh[4][2], bl[4][2];
#pragma unroll
            for (int np = 0; np < 2; np++) {
                uint32_t off = bOff + (np * 16 * LDA + k0) * 2;
                LDSM_X4(bh[2 * np][0], bh[2 * np][1],
                        bh[2 * np + 1][0], bh[2 * np + 1][1], sBh + off);
                LDSM_X4(bl[2 * np][0], bl[2 * np][1],
                        bl[2 * np + 1][0], bl[2 * np + 1][1], sBl + off);
            }
#pragma unroll
            for (int mt = 0; mt < 4; mt++) {
                uint32_t off = aOff + (mt * 16 * LDA + k0) * 2;
                uint32_t ah[4], al[4];
                LDSM_X4(ah[0], ah[1], ah[2], ah[3], sAh + off);
                LDSM_X4(al[0], al[1], al[2], al[3], sAl + off);
#pragma unroll
                for (int nt = 0; nt < 4; nt++) {
                    mma16816(acc[mt][nt], ah, bh[nt]);
                    mma16816(acc[mt][nt], ah, bl[nt]);
                    mma16816(acc[mt][nt], al, bh[nt]);
                }
            }
        }
        __syncthreads();
    }

    // Epilogue
#pragma unroll
    for (int mt = 0; mt < 4; mt++) {
        int m1 = m0 + wm + mt * 16 + gid;
        int m2 = m1 + 8;
        int b1i = 0, b2i = 0;
        if (ACT == 0) {
            b1i = (m1 < M) ? __ldg(&batch[m1]) : 0;
            b2i = (m2 < M) ? __ldg(&batch[m2]) : 0;
        }
#pragma unroll
        for (int nt = 0; nt < 4; nt++) {
            int n = n0 + wn + nt * 8 + 2 * tig;
            float2 bb = *(const float2*)(bias + n);
            float f0 = acc[mt][nt][0] + bb.x;
            float f1 = acc[mt][nt][1] + bb.y;
            float f2 = acc[mt][nt][2] + bb.x;
            float f3 = acc[mt][nt][3] + bb.y;
            if (ACT == 1) {
                f0 = f0 > 0.f ? f0 : 1.5f * f0;
                f1 = f1 > 0.f ? f1 : 1.5f * f1;
                f2 = f2 > 0.f ? f2 : 1.5f * f2;
                f3 = f3 > 0.f ? f3 : 1.5f * f3;
            } else if (ACT == 2) {
                f0 = fmaxf(f0, 0.f); f1 = fmaxf(f1, 0.f);
                f2 = fmaxf(f2, 0.f); f3 = fmaxf(f3, 0.f);
            }
            if (ACT == 0) {
                if (m1 < M) red_v2(&g_pool[b1i * DH + n], f0, f1);
                if (m2 < M) red_v2(&g_pool[b2i * DH + n], f2, f3);
            } else {
                if (m1 < M) {
                    __nv_bfloat16 h0 = __float2bfloat16(f0);
                    __nv_bfloat16 h1 = __float2bfloat16(f1);
                    __nv_bfloat162 hp; hp.x = h0; hp.y = h1;
                    __nv_bfloat162 lp;
                    lp.x = __float2bfloat16(f0 - __bfloat162float(h0));
                    lp.y = __float2bfloat16(f1 - __bfloat162float(h1));
                    *(__nv_bfloat162*)(Oh + (size_t)m1 * DH + n) = hp;
                    *(__nv_bfloat162*)(Ol + (size_t)m1 * DH + n) = lp;
                }
                if (m2 < M) {
                    __nv_bfloat16 h2 = __float2bfloat16(f2);
                    __nv_bfloat16 h3 = __float2bfloat16(f3);
                    __nv_bfloat162 hp; hp.x = h2; hp.y = h3;
                    __nv_bfloat162 lp;
                    lp.x = __float2bfloat16(f2 - __bfloat162float(h2));
                    lp.y = __float2bfloat16(f3 - __bfloat162float(h3));
                    *(__nv_bfloat162*)(Oh + (size_t)m2 * DH + n) = hp;
                    *(__nv_bfloat162*)(Ol + (size_t)m2 * DH + n) = lp;
                }
            }
        }
    }
}

// ---------------------------------------------------------------------------
__global__ void zero_pool_kernel() {
    int i = blockIdx.x * blockDim.x + threadIdx.x;
    if (i < GG * DH) g_pool[i] = 0.f;
    if (i < GG) g_cnt[i] = 0.f;
}

__global__ void count_kernel(const int* __restrict__ batch) {
    int i = blockIdx.x * blockDim.x + threadIdx.x;
    if (i < NN) atomicAdd(&g_cnt[__ldg(&batch[i])], 1.0f);
}

__global__ void final_out_kernel(const float* __restrict__ Wl,
                                 const float* __restrict__ bl,
                                 float* __restrict__ out) {
    __shared__ float p[DH];
    __shared__ float red[DOUT];
    int g = blockIdx.x;
    int t = threadIdx.x;

    float inv_cnt = 1.0f / fmaxf(g_cnt[g], 1.0f);
    for (int k = t; k < DH; k += DOUT)
        p[k] = g_pool[g * DH + k] * inv_cnt;
    __syncthreads();

    float acc = bl[t];
#pragma unroll 8
    for (int k = 0; k < DH; k++)
        acc += p[k] * Wl[k * DOUT + t];

    red[t] = acc * acc;
    __syncthreads();
    for (int s = DOUT / 2; s > 0; s >>= 1) {
        if (t < s) red[t] += red[t + s];
        __syncthreads();
    }
    float nrm = fmaxf(sqrtf(red[0]), 1e-12f);
    out[g * DOUT + t] = acc / nrm;
}

// ---------------------------------------------------------------------------
extern "C" void kernel_launch(void* const* d_in, const int* in_sizes, int n_in,
                              void* d_out, int out_size) {
    const float* x     = (const float*)d_in[0];
    const int*   ei    = (const int*)d_in[1];
    const int*   batch = (const int*)d_in[2];
    const float* W1 = (const float*)d_in[3];
    const float* b1 = (const float*)d_in[4];
    const float* W2 = (const float*)d_in[5];
    const float* b2 = (const float*)d_in[6];
    const float* W3 = (const float*)d_in[7];
    const float* b3 = (const float*)d_in[8];
    const float* W4 = (const float*)d_in[9];
    const float* b4 = (const float*)d_in[10];
    const float* Wl = (const float*)d_in[11];
    const float* bl = (const float*)d_in[12];
    float* out = (float*)d_out;

    __nv_bfloat16 *a0h, *a0l, *a1h, *a1l;
    __nv_bfloat16 *w1h, *w1l, *w2h, *w2l, *w3h, *w3l, *w4h, *w4l;
    cudaGetSymbolAddress((void**)&a0h, g_a0h);
    cudaGetSymbolAddress((void**)&a0l, g_a0l);
    cudaGetSymbolAddress((void**)&a1h, g_a1h);
    cudaGetSymbolAddress((void**)&a1l, g_a1l);
    cudaGetSymbolAddress((void**)&w1h, g_w1h);
    cudaGetSymbolAddress((void**)&w1l, g_w1l);
    cudaGetSymbolAddress((void**)&w2h, g_w2h);
    cudaGetSymbolAddress((void**)&w2l, g_w2l);
    cudaGetSymbolAddress((void**)&w3h, g_w3h);
    cudaGetSymbolAddress((void**)&w3l, g_w3l);
    cudaGetSymbolAddress((void**)&w4h, g_w4h);
    cudaGetSymbolAddress((void**)&w4l, g_w4l);

    cudaFuncSetAttribute(gemm_mma_kernel<0>, cudaFuncAttributeMaxDynamicSharedMemorySize, GEMM_SMEM);
    cudaFuncSetAttribute(gemm_mma_kernel<1>, cudaFuncAttributeMaxDynamicSharedMemorySize, GEMM_SMEM);
    cudaFuncSetAttribute(gemm_mma_kernel<2>, cudaFuncAttributeMaxDynamicSharedMemorySize, GEMM_SMEM);

    // 1) CSR build + fused aggregation/split (launch #6 = csr_agg, for ncu)
    zero_deg_kernel<<<(NN + 255) / 256, 256>>>();
    hist_kernel<<<(EE + 255) / 256, 256>>>(ei);
    scan1_kernel<<<NBLK, 256>>>();
    scan2_kernel<<<1, 256>>>();
    scatter_kernel<<<(EE + 255) / 256, 256>>>(ei);
    csr_agg_kernel<<<(NN * 32 + 255) / 256, 256>>>(x);

    // 2) weight transpose + split; pool init + counts
    splitW_kernel<<<(512 * DIN + 255) / 256, 256>>>(W1, DIN, w1h, w1l);
    splitW_kernel<<<(512 * DH + 255) / 256, 256>>>(W2, DH, w2h, w2l);
    splitW_kernel<<<(512 * DH + 255) / 256, 256>>>(W3, DH, w3h, w3l);
    splitW_kernel<<<(512 * DH + 255) / 256, 256>>>(W4, DH, w4h, w4l);
    zero_pool_kernel<<<(GG * DH + 255) / 256, 256>>>();
    count_kernel<<<(NN + 255) / 256, 256>>>(batch);

    // 3) 4-layer MLP; layer 4 fuses mean-pool red.v2
    dim3 grid(DH / 128, (NN + 127) / 128);
    gemm_mma_kernel<1><<<grid, 256, GEMM_SMEM>>>(a0h, a0l, w1h, w1l, b1, a1h, a1l, nullptr, NN, DIN);
    gemm_mma_kernel<2><<<grid, 256, GEMM_SMEM>>>(a1h, a1l, w2h, w2l, b2, a0h, a0l, nullptr, NN, DH);
    gemm_mma_kernel<2><<<grid, 256, GEMM_SMEM>>>(a0h, a0l, w3h, w3l, b3, a1h, a1l, nullptr, NN, DH);
    gemm_mma_kernel<0><<<grid, 256, GEMM_SMEM>>>(a1h, a1l, w4h, w4l, b4, nullptr, nullptr, batch, NN, DH);

    // 4) final linear + L2 normalize
    final_out_kernel<<<GG, DOUT>>>(Wl, bl, out);
}

// round 10
// speedup vs baseline: 4.1368x; 1.3287x over previous
#include <cuda_runtime.h>
#include <cuda_fp16.h>
#include <cstdint>

#define NN   50000
#define EE   800000
#define DIN  128
#define DH   512
#define DOUT 256
#define GG   512
#define NBLK 196                      // ceil(NN/256)

// ---------------------------------------------------------------------------
__device__ __align__(16) float g_pool[GG * DH];
__device__ float g_cnt[GG];

// CSR scratch
__device__ int g_deg[NN];
__device__ int g_fill[NN];
__device__ int g_offs[NN];
__device__ int g_bsum[256];
__device__ int g_eidx[EE];

// Activation ping-pong, single fp16
__device__ __align__(16) __half g_a0[NN * DH];
__device__ __align__(16) __half g_a1[NN * DH];

// Weights, transposed to [n][k], fp16 hi/lo split
__device__ __align__(16) __half g_w1h[DH * DIN], g_w1l[DH * DIN];
__device__ __align__(16) __half g_w2h[DH * DH],  g_w2l[DH * DH];
__device__ __align__(16) __half g_w3h[DH * DH],  g_w3l[DH * DH];
__device__ __align__(16) __half g_w4h[DH * DH],  g_w4l[DH * DH];

// ---------------------------------------------------------------------------
__device__ __forceinline__ uint32_t smem_u32(const void* p) {
    uint32_t a;
    asm("{ .reg .u64 t; cvta.to.shared.u64 t, %1; cvt.u32.u64 %0, t; }"
        : "=r"(a) : "l"(p));
    return a;
}
#define CP16(dst, src) \
    asm volatile("cp.async.cg.shared.global [%0], [%1], 16;" :: "r"(dst), "l"(src))
#define CP_COMMIT() asm volatile("cp.async.commit_group;" ::: "memory")
#define CP_WAIT0()  asm volatile("cp.async.wait_group 0;" ::: "memory")
#define CP_WAIT1()  asm volatile("cp.async.wait_group 1;" ::: "memory")
#define LDSM_X4(r0, r1, r2, r3, addr) \
    asm volatile("ldmatrix.sync.aligned.m8n8.x4.shared.b16 {%0,%1,%2,%3}, [%4];" \
                 : "=r"(r0), "=r"(r1), "=r"(r2), "=r"(r3) : "r"(addr))

__device__ __forceinline__ void red_v2(float* p, float a, float b) {
    asm volatile("red.global.add.v2.f32 [%0], {%1,%2};"
                 :: "l"(p), "f"(a), "f"(b) : "memory");
}

__device__ __forceinline__ void mma16816(float* d, const uint32_t* a,
                                         const uint32_t* b) {
    asm volatile(
        "mma.sync.aligned.m16n8k16.row.col.f32.f16.f16.f32 "
        "{%0,%1,%2,%3}, {%4,%5,%6,%7}, {%8,%9}, {%0,%1,%2,%3};"
        : "+f"(d[0]), "+f"(d[1]), "+f"(d[2]), "+f"(d[3])
        : "r"(a[0]), "r"(a[1]), "r"(a[2]), "r"(a[3]), "r"(b[0]), "r"(b[1]));
}

// ---------------------------------------------------------------------------
// CSR build
__global__ void zero_deg_kernel() {
    int i = blockIdx.x * blockDim.x + threadIdx.x;
    if (i < NN) { g_deg[i] = 0; g_fill[i] = 0; }
}

__global__ void hist_kernel(const int* __restrict__ ei) {
    int i = blockIdx.x * blockDim.x + threadIdx.x;
    if (i < EE) atomicAdd(&g_deg[__ldg(&ei[EE + i])], 1);
}

__global__ void scan1_kernel() {
    __shared__ int s[256];
    int tid = threadIdx.x;
    int idx = blockIdx.x * 256 + tid;
    int v = (idx < NN) ? g_deg[idx] : 0;
    s[tid] = v;
    __syncthreads();
#pragma unroll
    for (int d = 1; d < 256; d <<= 1) {
        int t = (tid >= d) ? s[tid - d] : 0;
        __syncthreads();
        s[tid] += t;
        __syncthreads();
    }
    if (idx < NN) g_offs[idx] = s[tid] - v;
    if (tid == 255) g_bsum[blockIdx.x] = s[255];
}

__global__ void scan2_kernel() {
    __shared__ int s[256];
    int tid = threadIdx.x;
    int v = (tid < NBLK) ? g_bsum[tid] : 0;
    s[tid] = v;
    __syncthreads();
#pragma unroll
    for (int d = 1; d < 256; d <<= 1) {
        int t = (tid >= d) ? s[tid - d] : 0;
        __syncthreads();
        s[tid] += t;
        __syncthreads();
    }
    g_bsum[tid] = s[tid] - v;
}

__global__ void scatter_kernel(const int* __restrict__ ei) {
    int e = blockIdx.x * blockDim.x + threadIdx.x;
    if (e >= EE) return;
    int src = __ldg(&ei[e]);
    int dst = __ldg(&ei[EE + e]);
    int pos = g_offs[dst] + g_bsum[dst >> 8] + atomicAdd(&g_fill[dst], 1);
    g_eidx[pos] = src;
}

// warp-per-node: acc = x[n] + sum_j x[eidx[j]]; emit fp16 directly
__global__ void csr_agg_kernel(const float* __restrict__ x) {
    int n = (blockIdx.x * blockDim.x + threadIdx.x) >> 5;
    if (n >= NN) return;
    int lane = threadIdx.x & 31;
    int base = g_offs[n] + g_bsum[n >> 8];
    int deg = g_deg[n];
    const float4* xr = (const float4*)x;

    float4 acc = __ldg(&xr[(size_t)n * 32 + lane]);
#pragma unroll 4
    for (int j = 0; j < deg; j++) {
        int s = __ldg(&g_eidx[base + j]);
        float4 v = __ldg(&xr[(size_t)s * 32 + lane]);
        acc.x += v.x; acc.y += v.y; acc.z += v.z; acc.w += v.w;
    }

    __half2 h01 = __floats2half2_rn(acc.x, acc.y);
    __half2 h23 = __floats2half2_rn(acc.z, acc.w);
    ((uint2*)(g_a0 + (size_t)n * DIN))[lane] =
        make_uint2(*(uint32_t*)&h01, *(uint32_t*)&h23);
}

// ---------------------------------------------------------------------------
__global__ void splitW_kernel(const float* __restrict__ W, int Kd,
                              __half* __restrict__ oh,
                              __half* __restrict__ ol) {
    int i = blockIdx.x * blockDim.x + threadIdx.x;
    if (i >= 512 * Kd) return;
    int n = i / Kd;
    int k = i - n * Kd;
    float f = W[(size_t)k * 512 + n];
    __half h = __float2half_rn(f);
    __half l = __float2half_rn(f - __half2float(h));
    oh[i] = h;
    ol[i] = l;
}

// ---------------------------------------------------------------------------
#define LDA         40
#define TILE_BYTES  (128 * LDA * 2)            // 10240
#define BUF_BYTES   (3 * TILE_BYTES)           // 30720 (A, Bh, Bl)
#define GEMM_SMEM   (2 * BUF_BYTES)            // 61440

__device__ __forceinline__ void issue_chunk(uint32_t sb,
                                            const __half* __restrict__ A,
                                            const __half* __restrict__ Bh,
                                            const __half* __restrict__ Bl,
                                            int m0, int n0, int M, int Kd, int kb,
                                            int tid) {
#pragma unroll
    for (int j = 0; j < 2; j++) {
        int idx = tid + 256 * j;
        int row = idx >> 2;
        int seg = idx & 3;
        uint32_t doff = row * (LDA * 2) + seg * 16;
        int ar = m0 + row;
        if (ar >= M) ar = M - 1;
        int br = n0 + row;
        size_t ko = (size_t)kb + seg * 8;
        CP16(sb + 0 * TILE_BYTES + doff, A + (size_t)ar * Kd + ko);
        CP16(sb + 1 * TILE_BYTES + doff, Bh + (size_t)br * Kd + ko);
        CP16(sb + 2 * TILE_BYTES + doff, Bl + (size_t)br * Kd + ko);
    }
}

// C = act(A @ (Bh+Bl)^T + bias), 2 MMA passes. CTA 128x128, 8 warps 2x4.
// ACT: 0 -> fused mean-pool red.v2; 1 -> LeakyReLU(1.5); 2 -> ReLU.
template <int ACT>
__global__ __launch_bounds__(256, 2)
void gemm_mma_kernel(const __half* __restrict__ A,
                     const __half* __restrict__ Bh,
                     const __half* __restrict__ Bl,
                     const float* __restrict__ bias,
                     __half* __restrict__ O,
                     const int* __restrict__ batch,
                     int M, int Kd) {
    extern __shared__ char smem[];
    const uint32_t s0 = smem_u32(smem);

    const int tid  = threadIdx.x;
    const int warp = tid >> 5;
    const int lane = tid & 31;
    const int gid  = lane >> 2;
    const int tig  = lane & 3;
    const int wm = (warp >> 2) * 64;
    const int wn = (warp & 3) * 32;
    const int m0 = blockIdx.y * 128;
    const int n0 = blockIdx.x * 128;

    const uint32_t aOff =
        ((wm + (lane & 15)) * LDA + ((lane >> 4) << 3)) * 2;
    const uint32_t bOff =
        ((wn + (lane & 7) + (((lane >> 4) & 1) << 3)) * LDA + (((lane >> 3) & 1) << 3)) * 2;

    float acc[4][4][4] = {};

    const int NCHUNK = Kd >> 5;

    issue_chunk(s0, A, Bh, Bl, m0, n0, M, Kd, 0, tid);
    CP_COMMIT();

    for (int c = 0; c < NCHUNK; c++) {
        const uint32_t sb = s0 + (c & 1) * BUF_BYTES;
        const bool has_next = (c + 1 < NCHUNK);
        if (has_next) {
            issue_chunk(s0 + ((c + 1) & 1) * BUF_BYTES, A, Bh, Bl,
                        m0, n0, M, Kd, (c + 1) * 32, tid);
            CP_COMMIT();
            CP_WAIT1();
        } else {
            CP_WAIT0();
        }
        __syncthreads();

        const uint32_t sA = sb;
        const uint32_t sBh = sb + TILE_BYTES, sBl = sb + 2 * TILE_BYTES;

#pragma unroll
        for (int k0 = 0; k0 < 32; k0 += 16) {
            uint32_t bh[4][2], bl[4][2];
#pragma unroll
            for (int np = 0; np < 2; np++) {
                uint32_t off = bOff + (np * 16 * LDA + k0) * 2;
                LDSM_X4(bh[2 * np][0], bh[2 * np][1],
                        bh[2 * np + 1][0], bh[2 * np + 1][1], sBh + off);
                LDSM_X4(bl[2 * np][0], bl[2 * np][1],
                        bl[2 * np + 1][0], bl[2 * np + 1][1], sBl + off);
            }
#pragma unroll
            for (int mt = 0; mt < 4; mt++) {
                uint32_t off = aOff + (mt * 16 * LDA + k0) * 2;
                uint32_t a[4];
                LDSM_X4(a[0], a[1], a[2], a[3], sA + off);
#pragma unroll
                for (int nt = 0; nt < 4; nt++) {
                    mma16816(acc[mt][nt], a, bh[nt]);
                    mma16816(acc[mt][nt], a, bl[nt]);
                }
            }
        }
        __syncthreads();
    }

    // Epilogue
#pragma unroll
    for (int mt = 0; mt < 4; mt++) {
        int m1 = m0 + wm + mt * 16 + gid;
        int m2 = m1 + 8;
        int b1i = 0, b2i = 0;
        if (ACT == 0) {
            b1i = (m1 < M) ? __ldg(&batch[m1]) : 0;
            b2i = (m2 < M) ? __ldg(&batch[m2]) : 0;
        }
#pragma unroll
        for (int nt = 0; nt < 4; nt++) {
            int n = n0 + wn + nt * 8 + 2 * tig;
            float2 bb = *(const float2*)(bias + n);
            float f0 = acc[mt][nt][0] + bb.x;
            float f1 = acc[mt][nt][1] + bb.y;
            float f2 = acc[mt][nt][2] + bb.x;
            float f3 = acc[mt][nt][3] + bb.y;
            if (ACT == 1) {
                f0 = f0 > 0.f ? f0 : 1.5f * f0;
                f1 = f1 > 0.f ? f1 : 1.5f * f1;
                f2 = f2 > 0.f ? f2 : 1.5f * f2;
                f3 = f3 > 0.f ? f3 : 1.5f * f3;
            } else if (ACT == 2) {
                f0 = fmaxf(f0, 0.f); f1 = fmaxf(f1, 0.f);
                f2 = fmaxf(f2, 0.f); f3 = fmaxf(f3, 0.f);
            }
            if (ACT == 0) {
                if (m1 < M) red_v2(&g_pool[b1i * DH + n], f0, f1);
                if (m2 < M) red_v2(&g_pool[b2i * DH + n], f2, f3);
            } else {
                if (m1 < M) {
                    __half2 hp = __floats2half2_rn(f0, f1);
                    *(__half2*)(O + (size_t)m1 * DH + n) = hp;
                }
                if (m2 < M) {
                    __half2 hp = __floats2half2_rn(f2, f3);
                    *(__half2*)(O + (size_t)m2 * DH + n) = hp;
                }
            }
        }
    }
}

// ---------------------------------------------------------------------------
__global__ void zero_pool_kernel() {
    int i = blockIdx.x * blockDim.x + threadIdx.x;
    if (i < GG * DH) g_pool[i] = 0.f;
    if (i < GG) g_cnt[i] = 0.f;
}

__global__ void count_kernel(const int* __restrict__ batch) {
    int i = blockIdx.x * blockDim.x + threadIdx.x;
    if (i < NN) atomicAdd(&g_cnt[__ldg(&batch[i])], 1.0f);
}

__global__ void final_out_kernel(const float* __restrict__ Wl,
                                 const float* __restrict__ bl,
                                 float* __restrict__ out) {
    __shared__ float p[DH];
    __shared__ float red[DOUT];
    int g = blockIdx.x;
    int t = threadIdx.x;

    float inv_cnt = 1.0f / fmaxf(g_cnt[g], 1.0f);
    for (int k = t; k < DH; k += DOUT)
        p[k] = g_pool[g * DH + k] * inv_cnt;
    __syncthreads();

    float acc = bl[t];
#pragma unroll 8
    for (int k = 0; k < DH; k++)
        acc += p[k] * Wl[k * DOUT + t];

    red[t] = acc * acc;
    __syncthreads();
    for (int s = DOUT / 2; s > 0; s >>= 1) {
        if (t < s) red[t] += red[t + s];
        __syncthreads();
    }
    float nrm = fmaxf(sqrtf(red[0]), 1e-12f);
    out[g * DOUT + t] = acc / nrm;
}

// ---------------------------------------------------------------------------
extern "C" void kernel_launch(void* const* d_in, const int* in_sizes, int n_in,
                              void* d_out, int out_size) {
    const float* x     = (const float*)d_in[0];
    const int*   ei    = (const int*)d_in[1];
    const int*   batch = (const int*)d_in[2];
    const float* W1 = (const float*)d_in[3];
    const float* b1 = (const float*)d_in[4];
    const float* W2 = (const float*)d_in[5];
    const float* b2 = (const float*)d_in[6];
    const float* W3 = (const float*)d_in[7];
    const float* b3 = (const float*)d_in[8];
    const float* W4 = (const float*)d_in[9];
    const float* b4 = (const float*)d_in[10];
    const float* Wl = (const float*)d_in[11];
    const float* bl = (const float*)d_in[12];
    float* out = (float*)d_out;

    __half *a0, *a1;
    __half *w1h, *w1l, *w2h, *w2l, *w3h, *w3l, *w4h, *w4l;
    cudaGetSymbolAddress((void**)&a0, g_a0);
    cudaGetSymbolAddress((void**)&a1, g_a1);
    cudaGetSymbolAddress((void**)&w1h, g_w1h);
    cudaGetSymbolAddress((void**)&w1l, g_w1l);
    cudaGetSymbolAddress((void**)&w2h, g_w2h);
    cudaGetSymbolAddress((void**)&w2l, g_w2l);
    cudaGetSymbolAddress((void**)&w3h, g_w3h);
    cudaGetSymbolAddress((void**)&w3l, g_w3l);
    cudaGetSymbolAddress((void**)&w4h, g_w4h);
    cudaGetSymbolAddress((void**)&w4l, g_w4l);

    cudaFuncSetAttribute(gemm_mma_kernel<0>, cudaFuncAttributeMaxDynamicSharedMemorySize, GEMM_SMEM);
    cudaFuncSetAttribute(gemm_mma_kernel<1>, cudaFuncAttributeMaxDynamicSharedMemorySize, GEMM_SMEM);
    cudaFuncSetAttribute(gemm_mma_kernel<2>, cudaFuncAttributeMaxDynamicSharedMemorySize, GEMM_SMEM);

    // 1) CSR build + fused aggregation/fp16 convert
    zero_deg_kernel<<<(NN + 255) / 256, 256>>>();
    hist_kernel<<<(EE + 255) / 256, 256>>>(ei);
    scan1_kernel<<<NBLK, 256>>>();
    scan2_kernel<<<1, 256>>>();
    scatter_kernel<<<(EE + 255) / 256, 256>>>(ei);
    csr_agg_kernel<<<(NN * 32 + 255) / 256, 256>>>(x);

    // 2) weight transpose + hi/lo split; pool init + counts
    splitW_kernel<<<(512 * DIN + 255) / 256, 256>>>(W1, DIN, w1h, w1l);
    splitW_kernel<<<(512 * DH + 255) / 256, 256>>>(W2, DH, w2h, w2l);
    splitW_kernel<<<(512 * DH + 255) / 256, 256>>>(W3, DH, w3h, w3l);
    splitW_kernel<<<(512 * DH + 255) / 256, 256>>>(W4, DH, w4h, w4l);
    zero_pool_kernel<<<(GG * DH + 255) / 256, 256>>>();
    count_kernel<<<(NN + 255) / 256, 256>>>(batch);

    // 3) 4-layer MLP (fp16 2-pass); layer 4 fuses mean-pool red.v2
    dim3 grid(DH / 128, (NN + 127) / 128);
    gemm_mma_kernel<1><<<grid, 256, GEMM_SMEM>>>(a0, w1h, w1l, b1, a1, nullptr, NN, DIN);
    gemm_mma_kernel<2><<<grid, 256, GEMM_SMEM>>>(a1, w2h, w2l, b2, a0, nullptr, NN, DH);
    gemm_mma_kernel<2><<<grid, 256, GEMM_SMEM>>>(a0, w3h, w3l, b3, a1, nullptr, NN, DH);
    gemm_mma_kernel<0><<<grid, 256, GEMM_SMEM>>>(a1, w4h, w4l, b4, nullptr, batch, NN, DH);

    // 4) final linear + L2 normalize
    final_out_kernel<<<GG, DOUT>>>(Wl, bl, out);
}

// round 11
// speedup vs baseline: 5.6937x; 1.3764x over previous
#include <cuda_runtime.h>
#include <cuda_fp16.h>
#include <cstdint>

#define NN   50000
#define EE   800000
#define DIN  128
#define DH   512
#define DOUT 256
#define GG   512
#define NBLK 196                      // ceil(NN/256)

// ---------------------------------------------------------------------------
__device__ __align__(16) float g_pool[GG * DH];
__device__ float g_cnt[GG];

// CSR scratch
__device__ int g_deg[NN];
__device__ int g_fill[NN];
__device__ int g_offs[NN];
__device__ int g_bsum[256];
__device__ int g_eidx[EE];

// Activation ping-pong, fp16
__device__ __align__(16) __half g_a0[NN * DH];
__device__ __align__(16) __half g_a1[NN * DH];

// Weights, transposed to [n][k], single fp16
__device__ __align__(16) __half g_w1[DH * DIN];
__device__ __align__(16) __half g_w2[DH * DH];
__device__ __align__(16) __half g_w3[DH * DH];
__device__ __align__(16) __half g_w4[DH * DH];

// ---------------------------------------------------------------------------
__device__ __forceinline__ uint32_t smem_u32(const void* p) {
    uint32_t a;
    asm("{ .reg .u64 t; cvta.to.shared.u64 t, %1; cvt.u32.u64 %0, t; }"
        : "=r"(a) : "l"(p));
    return a;
}
#define CP16(dst, src) \
    asm volatile("cp.async.cg.shared.global [%0], [%1], 16;" :: "r"(dst), "l"(src))
#define CP_COMMIT() asm volatile("cp.async.commit_group;" ::: "memory")
#define CP_WAIT0()  asm volatile("cp.async.wait_group 0;" ::: "memory")
#define CP_WAIT1()  asm volatile("cp.async.wait_group 1;" ::: "memory")
#define LDSM_X4(r0, r1, r2, r3, addr) \
    asm volatile("ldmatrix.sync.aligned.m8n8.x4.shared.b16 {%0,%1,%2,%3}, [%4];" \
                 : "=r"(r0), "=r"(r1), "=r"(r2), "=r"(r3) : "r"(addr))

__device__ __forceinline__ void red_v2(float* p, float a, float b) {
    asm volatile("red.global.add.v2.f32 [%0], {%1,%2};"
                 :: "l"(p), "f"(a), "f"(b) : "memory");
}

__device__ __forceinline__ void mma16816(float* d, const uint32_t* a,
                                         const uint32_t* b) {
    asm volatile(
        "mma.sync.aligned.m16n8k16.row.col.f32.f16.f16.f32 "
        "{%0,%1,%2,%3}, {%4,%5,%6,%7}, {%8,%9}, {%0,%1,%2,%3};"
        : "+f"(d[0]), "+f"(d[1]), "+f"(d[2]), "+f"(d[3])
        : "r"(a[0]), "r"(a[1]), "r"(a[2]), "r"(a[3]), "r"(b[0]), "r"(b[1]));
}

// ---------------------------------------------------------------------------
// CSR build
__global__ void zero_deg_kernel() {
    int i = blockIdx.x * blockDim.x + threadIdx.x;
    if (i < NN) { g_deg[i] = 0; g_fill[i] = 0; }
}

__global__ void hist_kernel(const int* __restrict__ ei) {
    int i = blockIdx.x * blockDim.x + threadIdx.x;
    if (i < EE) atomicAdd(&g_deg[__ldg(&ei[EE + i])], 1);
}

__global__ void scan1_kernel() {
    __shared__ int s[256];
    int tid = threadIdx.x;
    int idx = blockIdx.x * 256 + tid;
    int v = (idx < NN) ? g_deg[idx] : 0;
    s[tid] = v;
    __syncthreads();
#pragma unroll
    for (int d = 1; d < 256; d <<= 1) {
        int t = (tid >= d) ? s[tid - d] : 0;
        __syncthreads();
        s[tid] += t;
        __syncthreads();
    }
    if (idx < NN) g_offs[idx] = s[tid] - v;
    if (tid == 255) g_bsum[blockIdx.x] = s[255];
}

__global__ void scan2_kernel() {
    __shared__ int s[256];
    int tid = threadIdx.x;
    int v = (tid < NBLK) ? g_bsum[tid] : 0;
    s[tid] = v;
    __syncthreads();
#pragma unroll
    for (int d = 1; d < 256; d <<= 1) {
        int t = (tid >= d) ? s[tid - d] : 0;
        __syncthreads();
        s[tid] += t;
        __syncthreads();
    }
    g_bsum[tid] = s[tid] - v;
}

__global__ void scatter_kernel(const int* __restrict__ ei) {
    int e = blockIdx.x * blockDim.x + threadIdx.x;
    if (e >= EE) return;
    int src = __ldg(&ei[e]);
    int dst = __ldg(&ei[EE + e]);
    int pos = g_offs[dst] + g_bsum[dst >> 8] + atomicAdd(&g_fill[dst], 1);
    g_eidx[pos] = src;
}

// warp-per-node: acc = x[n] + sum_j x[eidx[j]]; emit fp16 directly
__global__ void csr_agg_kernel(const float* __restrict__ x) {
    int n = (blockIdx.x * blockDim.x + threadIdx.x) >> 5;
    if (n >= NN) return;
    int lane = threadIdx.x & 31;
    int base = g_offs[n] + g_bsum[n >> 8];
    int deg = g_deg[n];
    const float4* xr = (const float4*)x;

    float4 acc = __ldg(&xr[(size_t)n * 32 + lane]);
#pragma unroll 4
    for (int j = 0; j < deg; j++) {
        int s = __ldg(&g_eidx[base + j]);
        float4 v = __ldg(&xr[(size_t)s * 32 + lane]);
        acc.x += v.x; acc.y += v.y; acc.z += v.z; acc.w += v.w;
    }

    __half2 h01 = __floats2half2_rn(acc.x, acc.y);
    __half2 h23 = __floats2half2_rn(acc.z, acc.w);
    ((uint2*)(g_a0 + (size_t)n * DIN))[lane] =
        make_uint2(*(uint32_t*)&h01, *(uint32_t*)&h23);
}

// ---------------------------------------------------------------------------
// W[k][n] -> Wt[n][k], single fp16
__global__ void convW_kernel(const float* __restrict__ W, int Kd,
                             __half* __restrict__ o) {
    int i = blockIdx.x * blockDim.x + threadIdx.x;
    if (i >= 512 * Kd) return;
    int n = i / Kd;
    int k = i - n * Kd;
    o[i] = __float2half_rn(W[(size_t)k * 512 + n]);
}

// ---------------------------------------------------------------------------
#define LDA         40
#define TILE_BYTES  (128 * LDA * 2)            // 10240
#define BUF_BYTES   (2 * TILE_BYTES)           // 20480 (A, B)
#define GEMM_SMEM   (2 * BUF_BYTES)            // 40960

__device__ __forceinline__ void issue_chunk(uint32_t sb,
                                            const __half* __restrict__ A,
                                            const __half* __restrict__ B,
                                            int m0, int n0, int M, int Kd, int kb,
                                            int tid) {
#pragma unroll
    for (int j = 0; j < 2; j++) {
        int idx = tid + 256 * j;
        int row = idx >> 2;
        int seg = idx & 3;
        uint32_t doff = row * (LDA * 2) + seg * 16;
        int ar = m0 + row;
        if (ar >= M) ar = M - 1;
        int br = n0 + row;
        size_t ko = (size_t)kb + seg * 8;
        CP16(sb + 0 * TILE_BYTES + doff, A + (size_t)ar * Kd + ko);
        CP16(sb + 1 * TILE_BYTES + doff, B + (size_t)br * Kd + ko);
    }
}

// C = act(A @ B^T + bias), single fp16 pass. CTA 128x128, 8 warps 2x4.
// ACT: 0 -> fused mean-pool red.v2; 1 -> LeakyReLU(1.5); 2 -> ReLU.
template <int ACT>
__global__ __launch_bounds__(256, 2)
void gemm_mma_kernel(const __half* __restrict__ A,
                     const __half* __restrict__ B,
                     const float* __restrict__ bias,
                     __half* __restrict__ O,
                     const int* __restrict__ batch,
                     int M, int Kd) {
    extern __shared__ char smem[];
    const uint32_t s0 = smem_u32(smem);

    const int tid  = threadIdx.x;
    const int warp = tid >> 5;
    const int lane = tid & 31;
    const int gid  = lane >> 2;
    const int tig  = lane & 3;
    const int wm = (warp >> 2) * 64;
    const int wn = (warp & 3) * 32;
    const int m0 = blockIdx.y * 128;
    const int n0 = blockIdx.x * 128;

    const uint32_t aOff =
        ((wm + (lane & 15)) * LDA + ((lane >> 4) << 3)) * 2;
    const uint32_t bOff =
        ((wn + (lane & 7) + (((lane >> 4) & 1) << 3)) * LDA + (((lane >> 3) & 1) << 3)) * 2;

    float acc[4][4][4] = {};

    const int NCHUNK = Kd >> 5;

    issue_chunk(s0, A, B, m0, n0, M, Kd, 0, tid);
    CP_COMMIT();

    for (int c = 0; c < NCHUNK; c++) {
        const uint32_t sb = s0 + (c & 1) * BUF_BYTES;
        const bool has_next = (c + 1 < NCHUNK);
        if (has_next) {
            issue_chunk(s0 + ((c + 1) & 1) * BUF_BYTES, A, B,
                        m0, n0, M, Kd, (c + 1) * 32, tid);
            CP_COMMIT();
            CP_WAIT1();
        } else {
            CP_WAIT0();
        }
        __syncthreads();

        const uint32_t sA = sb;
        const uint32_t sB = sb + TILE_BYTES;

#pragma unroll
        for (int k0 = 0; k0 < 32; k0 += 16) {
            uint32_t b[4][2];
#pragma unroll
            for (int np = 0; np < 2; np++) {
                uint32_t off = bOff + (np * 16 * LDA + k0) * 2;
                LDSM_X4(b[2 * np][0], b[2 * np][1],
                        b[2 * np + 1][0], b[2 * np + 1][1], sB + off);
            }
#pragma unroll
            for (int mt = 0; mt < 4; mt++) {
                uint32_t off = aOff + (mt * 16 * LDA + k0) * 2;
                uint32_t a[4];
                LDSM_X4(a[0], a[1], a[2], a[3], sA + off);
#pragma unroll
                for (int nt = 0; nt < 4; nt++)
                    mma16816(acc[mt][nt], a, b[nt]);
            }
        }
        __syncthreads();
    }

    // Epilogue
#pragma unroll
    for (int mt = 0; mt < 4; mt++) {
        int m1 = m0 + wm + mt * 16 + gid;
        int m2 = m1 + 8;
        int b1i = 0, b2i = 0;
        if (ACT == 0) {
            b1i = (m1 < M) ? __ldg(&batch[m1]) : 0;
            b2i = (m2 < M) ? __ldg(&batch[m2]) : 0;
        }
#pragma unroll
        for (int nt = 0; nt < 4; nt++) {
            int n = n0 + wn + nt * 8 + 2 * tig;
            float2 bb = *(const float2*)(bias + n);
            float f0 = acc[mt][nt][0] + bb.x;
            float f1 = acc[mt][nt][1] + bb.y;
            float f2 = acc[mt][nt][2] + bb.x;
            float f3 = acc[mt][nt][3] + bb.y;
            if (ACT == 1) {
                f0 = f0 > 0.f ? f0 : 1.5f * f0;
                f1 = f1 > 0.f ? f1 : 1.5f * f1;
                f2 = f2 > 0.f ? f2 : 1.5f * f2;
                f3 = f3 > 0.f ? f3 : 1.5f * f3;
            } else if (ACT == 2) {
                f0 = fmaxf(f0, 0.f); f1 = fmaxf(f1, 0.f);
                f2 = fmaxf(f2, 0.f); f3 = fmaxf(f3, 0.f);
            }
            if (ACT == 0) {
                if (m1 < M) red_v2(&g_pool[b1i * DH + n], f0, f1);
                if (m2 < M) red_v2(&g_pool[b2i * DH + n], f2, f3);
            } else {
                if (m1 < M) {
                    __half2 hp = __floats2half2_rn(f0, f1);
                    *(__half2*)(O + (size_t)m1 * DH + n) = hp;
                }
                if (m2 < M) {
                    __half2 hp = __floats2half2_rn(f2, f3);
                    *(__half2*)(O + (size_t)m2 * DH + n) = hp;
                }
            }
        }
    }
}

// ---------------------------------------------------------------------------
__global__ void zero_pool_kernel() {
    int i = blockIdx.x * blockDim.x + threadIdx.x;
    if (i < GG * DH) g_pool[i] = 0.f;
    if (i < GG) g_cnt[i] = 0.f;
}

__global__ void count_kernel(const int* __restrict__ batch) {
    int i = blockIdx.x * blockDim.x + threadIdx.x;
    if (i < NN) atomicAdd(&g_cnt[__ldg(&batch[i])], 1.0f);
}

__global__ void final_out_kernel(const float* __restrict__ Wl,
                                 const float* __restrict__ bl,
                                 float* __restrict__ out) {
    __shared__ float p[DH];
    __shared__ float red[DOUT];
    int g = blockIdx.x;
    int t = threadIdx.x;

    float inv_cnt = 1.0f / fmaxf(g_cnt[g], 1.0f);
    for (int k = t; k < DH; k += DOUT)
        p[k] = g_pool[g * DH + k] * inv_cnt;
    __syncthreads();

    float acc = bl[t];
#pragma unroll 8
    for (int k = 0; k < DH; k++)
        acc += p[k] * Wl[k * DOUT + t];

    red[t] = acc * acc;
    __syncthreads();
    for (int s = DOUT / 2; s > 0; s >>= 1) {
        if (t < s) red[t] += red[t + s];
        __syncthreads();
    }
    float nrm = fmaxf(sqrtf(red[0]), 1e-12f);
    out[g * DOUT + t] = acc / nrm;
}

// ---------------------------------------------------------------------------
extern "C" void kernel_launch(void* const* d_in, const int* in_sizes, int n_in,
                              void* d_out, int out_size) {
    const float* x     = (const float*)d_in[0];
    const int*   ei    = (const int*)d_in[1];
    const int*   batch = (const int*)d_in[2];
    const float* W1 = (const float*)d_in[3];
    const float* b1 = (const float*)d_in[4];
    const float* W2 = (const float*)d_in[5];
    const float* b2 = (const float*)d_in[6];
    const float* W3 = (const float*)d_in[7];
    const float* b3 = (const float*)d_in[8];
    const float* W4 = (const float*)d_in[9];
    const float* b4 = (const float*)d_in[10];
    const float* Wl = (const float*)d_in[11];
    const float* bl = (const float*)d_in[12];
    float* out = (float*)d_out;

    __half *a0, *a1, *w1, *w2, *w3, *w4;
    cudaGetSymbolAddress((void**)&a0, g_a0);
    cudaGetSymbolAddress((void**)&a1, g_a1);
    cudaGetSymbolAddress((void**)&w1, g_w1);
    cudaGetSymbolAddress((void**)&w2, g_w2);
    cudaGetSymbolAddress((void**)&w3, g_w3);
    cudaGetSymbolAddress((void**)&w4, g_w4);

    cudaFuncSetAttribute(gemm_mma_kernel<0>, cudaFuncAttributeMaxDynamicSharedMemorySize, GEMM_SMEM);
    cudaFuncSetAttribute(gemm_mma_kernel<1>, cudaFuncAttributeMaxDynamicSharedMemorySize, GEMM_SMEM);
    cudaFuncSetAttribute(gemm_mma_kernel<2>, cudaFuncAttributeMaxDynamicSharedMemorySize, GEMM_SMEM);

    // 1) CSR build + fused aggregation/fp16 convert
    zero_deg_kernel<<<(NN + 255) / 256, 256>>>();
    hist_kernel<<<(EE + 255) / 256, 256>>>(ei);
    scan1_kernel<<<NBLK, 256>>>();
    scan2_kernel<<<1, 256>>>();
    scatter_kernel<<<(EE + 255) / 256, 256>>>(ei);
    csr_agg_kernel<<<(NN * 32 + 255) / 256, 256>>>(x);

    // 2) weight transpose/convert; pool init + counts
    convW_kernel<<<(512 * DIN + 255) / 256, 256>>>(W1, DIN, w1);
    convW_kernel<<<(512 * DH + 255) / 256, 256>>>(W2, DH, w2);
    convW_kernel<<<(512 * DH + 255) / 256, 256>>>(W3, DH, w3);
    convW_kernel<<<(512 * DH + 255) / 256, 256>>>(W4, DH, w4);
    zero_pool_kernel<<<(GG * DH + 255) / 256, 256>>>();
    count_kernel<<<(NN + 255) / 256, 256>>>(batch);

    // 3) 4-layer MLP (single-pass fp16); layer 4 fuses mean-pool red.v2
    dim3 grid(DH / 128, (NN + 127) / 128);
    gemm_mma_kernel<1><<<grid, 256, GEMM_SMEM>>>(a0, w1, b1, a1, nullptr, NN, DIN);
    gemm_mma_kernel<2><<<grid, 256, GEMM_SMEM>>>(a1, w2, b2, a0, nullptr, NN, DH);
    gemm_mma_kernel<2><<<grid, 256, GEMM_SMEM>>>(a0, w3, b3, a1, nullptr, NN, DH);
    gemm_mma_kernel<0><<<grid, 256, GEMM_SMEM>>>(a1, w4, b4, nullptr, batch, NN, DH);

    // 4) final linear + L2 normalize
    final_out_kernel<<<GG, DOUT>>>(Wl, bl, out);
}